// round 12
// baseline (speedup 1.0000x reference)
#include <cuda_runtime.h>
#include <cuda_bf16.h>
#include <mma.h>
#include <float.h>
#include <math.h>

using namespace nvcuda;
typedef __nv_bfloat16 bf16;

#define BATCH 2
#define NSEQ  2048
#define DIM   1024
#define H     16
#define DH    64
#define NM    16
#define JTOT  2064          // NM + NSEQ
#define MROWS (BATCH*NSEQ)  // 4096

// ---------------- global scratch ----------------
__device__ float g_Q[BATCH][H][NSEQ][DH];
__device__ float g_K[BATCH][H][JTOT][DH];
__device__ float g_V[BATCH][H][JTOT][DH];
__device__ float g_dots[BATCH][H][NSEQ][JTOT];
__device__ bf16  g_xh[MROWS*DIM],  g_xl[MROWS*DIM];
__device__ bf16  g_Wvh[DIM*DIM],   g_Wvl[DIM*DIM];
__device__ bf16  g_Woh[DIM*DIM],   g_Wol[DIM*DIM];
__device__ bf16  g_ctxh[MROWS*DIM], g_ctxl[MROWS*DIM];

__device__ __forceinline__ void bsplit2(float v, bf16& h, bf16& l) {
    h = __float2bfloat16(v);
    l = __float2bfloat16(v - __bfloat162float(h));
}

// ---------------- fill mem_k / mem_v into K/V prefix ----------------
__global__ void memfill_kernel(const float* __restrict__ mk, const float* __restrict__ mv) {
    int idx = blockIdx.x * 256 + threadIdx.x;
    if (idx >= BATCH * H * NM * DH) return;
    int d = idx & 63;
    int j = (idx >> 6) & 15;
    int h = (idx >> 10) & 15;
    int b = idx >> 14;
    g_K[b][h][j][d] = mk[(h * NM + j) * DH + d];
    g_V[b][h][j][d] = mv[(h * NM + j) * DH + d];
}

// ---------------- bf16 hi/lo split ----------------
__global__ void split2(const float* __restrict__ s, bf16* __restrict__ h,
                       bf16* __restrict__ l, int n) {
    int i = blockIdx.x * 256 + threadIdx.x;
    if (i >= n) return;
    bf16 a, c; bsplit2(s[i], a, c);
    h[i] = a; l[i] = c;
}

// ============ 128x128x16 fp32 GEMM (Q,K only — bit-identical path) ============
__global__ __launch_bounds__(256, 2) void gemm_qkv_kernel(
    const float* __restrict__ x, const float* __restrict__ Wq,
    const float* __restrict__ Wk, const float* __restrict__ Wv) {
    const int z = blockIdx.z;
    const float* W = (z == 0) ? Wq : (z == 1) ? Wk : Wv;
    __shared__ float As[2][16][132];
    __shared__ float Bs[2][16][132];
    const int m0 = blockIdx.y << 7;
    const int n0 = blockIdx.x << 7;
    const int tid = threadIdx.x;
    const int ty = tid >> 4, tx = tid & 15;
    const int arow = tid >> 2, acol = (tid & 3) << 2;
    const int brow = tid >> 5, bcol = (tid & 31) << 2;
    float acc[8][8];
#pragma unroll
    for (int i = 0; i < 8; i++)
#pragma unroll
        for (int j = 0; j < 8; j++) acc[i][j] = 0.f;

    {
        float4 a0 = *(const float4*)&x[(m0 + arow) * DIM + acol];
        float4 a1 = *(const float4*)&x[(m0 + arow + 64) * DIM + acol];
        float4 b0 = *(const float4*)&W[brow * DIM + n0 + bcol];
        float4 b1 = *(const float4*)&W[(brow + 8) * DIM + n0 + bcol];
        As[0][acol + 0][arow] = a0.x; As[0][acol + 1][arow] = a0.y;
        As[0][acol + 2][arow] = a0.z; As[0][acol + 3][arow] = a0.w;
        As[0][acol + 0][arow + 64] = a1.x; As[0][acol + 1][arow + 64] = a1.y;
        As[0][acol + 2][arow + 64] = a1.z; As[0][acol + 3][arow + 64] = a1.w;
        *(float4*)&Bs[0][brow][bcol] = b0;
        *(float4*)&Bs[0][brow + 8][bcol] = b1;
    }
    __syncthreads();

    int cur = 0;
    for (int k0 = 0; k0 < DIM; k0 += 16) {
        const int nxt = k0 + 16;
        float4 na0, na1, nb0, nb1;
        if (nxt < DIM) {
            na0 = *(const float4*)&x[(m0 + arow) * DIM + nxt + acol];
            na1 = *(const float4*)&x[(m0 + arow + 64) * DIM + nxt + acol];
            nb0 = *(const float4*)&W[(nxt + brow) * DIM + n0 + bcol];
            nb1 = *(const float4*)&W[(nxt + brow + 8) * DIM + n0 + bcol];
        }
#pragma unroll
        for (int kk = 0; kk < 16; kk++) {
            float4 a04 = *(const float4*)&As[cur][kk][ty << 3];
            float4 a14 = *(const float4*)&As[cur][kk][(ty << 3) + 4];
            float4 b04 = *(const float4*)&Bs[cur][kk][tx << 3];
            float4 b14 = *(const float4*)&Bs[cur][kk][(tx << 3) + 4];
            float av[8] = {a04.x, a04.y, a04.z, a04.w, a14.x, a14.y, a14.z, a14.w};
            float bv[8] = {b04.x, b04.y, b04.z, b04.w, b14.x, b14.y, b14.z, b14.w};
#pragma unroll
            for (int i = 0; i < 8; i++)
#pragma unroll
                for (int j = 0; j < 8; j++) acc[i][j] += av[i] * bv[j];
        }
        if (nxt < DIM) {
            const int nb = cur ^ 1;
            As[nb][acol + 0][arow] = na0.x; As[nb][acol + 1][arow] = na0.y;
            As[nb][acol + 2][arow] = na0.z; As[nb][acol + 3][arow] = na0.w;
            As[nb][acol + 0][arow + 64] = na1.x; As[nb][acol + 1][arow + 64] = na1.y;
            As[nb][acol + 2][arow + 64] = na1.z; As[nb][acol + 3][arow + 64] = na1.w;
            *(float4*)&Bs[nb][brow][bcol] = nb0;
            *(float4*)&Bs[nb][brow + 8][bcol] = nb1;
            __syncthreads();
            cur = nb;
        }
    }
#pragma unroll
    for (int i = 0; i < 8; i++) {
        int m = m0 + (ty << 3) + i;
        int b = m >> 11;
        int irow = m & 2047;
#pragma unroll
        for (int j2 = 0; j2 < 8; j2 += 4) {
            int c = n0 + (tx << 3) + j2;
            int h = c >> 6;
            int d = c & 63;
            float4 v = make_float4(acc[i][j2], acc[i][j2 + 1], acc[i][j2 + 2], acc[i][j2 + 3]);
            if (z == 0)      *(float4*)&g_Q[b][h][irow][d] = v;
            else if (z == 1) *(float4*)&g_K[b][h][NM + irow][d] = v;
            else             *(float4*)&g_V[b][h][NM + irow][d] = v;
        }
    }
}

// ============ V projection: bf16x3 wmma (linear path) ============
__global__ __launch_bounds__(256) void v_wmma() {
    __shared__ bf16 sAh[128 * 40], sAl[128 * 40];
    __shared__ bf16 sBh[32 * 72],  sBl[32 * 72];
    const int m0 = blockIdx.y << 7;
    const int n0 = blockIdx.x << 6;
    const int tid = threadIdx.x;
    const int w = tid >> 5;
    const int wm = w >> 1, wn = w & 1;

    wmma::fragment<wmma::accumulator, 16, 16, 16, float> acc[2][2];
#pragma unroll
    for (int i = 0; i < 2; i++)
#pragma unroll
        for (int j = 0; j < 2; j++) wmma::fill_fragment(acc[i][j], 0.f);

    for (int k0 = 0; k0 < DIM; k0 += 32) {
        __syncthreads();
#pragma unroll
        for (int it = 0; it < 4; it++) {
            int idx = tid + it * 256;
            int r = idx >> 3, c = (idx & 7) << 2;
            long g = (long)(m0 + r) * DIM + k0 + c;
            *(uint2*)&sAh[r * 40 + c] = *(const uint2*)&g_xh[g];
            *(uint2*)&sAl[r * 40 + c] = *(const uint2*)&g_xl[g];
        }
#pragma unroll
        for (int it = 0; it < 2; it++) {
            int idx = tid + it * 256;
            int r = idx >> 4, c = (idx & 15) << 2;
            long g = (long)(k0 + r) * DIM + n0 + c;
            *(uint2*)&sBh[r * 72 + c] = *(const uint2*)&g_Wvh[g];
            *(uint2*)&sBl[r * 72 + c] = *(const uint2*)&g_Wvl[g];
        }
        __syncthreads();
#pragma unroll
        for (int ks = 0; ks < 2; ks++) {
            int k = ks << 4;
            wmma::fragment<wmma::matrix_a, 16, 16, 16, bf16, wmma::row_major> ah[2], al[2];
            wmma::fragment<wmma::matrix_b, 16, 16, 16, bf16, wmma::row_major> bh[2], bl[2];
#pragma unroll
            for (int fm = 0; fm < 2; fm++) {
                wmma::load_matrix_sync(ah[fm], &sAh[(wm * 32 + fm * 16) * 40 + k], 40);
                wmma::load_matrix_sync(al[fm], &sAl[(wm * 32 + fm * 16) * 40 + k], 40);
            }
#pragma unroll
            for (int fn = 0; fn < 2; fn++) {
                wmma::load_matrix_sync(bh[fn], &sBh[k * 72 + wn * 32 + fn * 16], 72);
                wmma::load_matrix_sync(bl[fn], &sBl[k * 72 + wn * 32 + fn * 16], 72);
            }
#pragma unroll
            for (int fm = 0; fm < 2; fm++)
#pragma unroll
                for (int fn = 0; fn < 2; fn++) {
                    wmma::mma_sync(acc[fm][fn], ah[fm], bl[fn], acc[fm][fn]);
                    wmma::mma_sync(acc[fm][fn], al[fm], bh[fn], acc[fm][fn]);
                    wmma::mma_sync(acc[fm][fn], ah[fm], bh[fn], acc[fm][fn]);
                }
        }
    }
    const int h = n0 >> 6;
#pragma unroll
    for (int fm = 0; fm < 2; fm++) {
        int m = m0 + wm * 32 + fm * 16;
        int b = m >> 11;
        int irow = m & 2047;
#pragma unroll
        for (int fn = 0; fn < 2; fn++) {
            int d = wn * 32 + fn * 16;
            wmma::store_matrix_sync(&g_V[b][h][NM + irow][d], acc[fm][fn], DH, wmma::mem_row_major);
        }
    }
}

// ============ dots: per (b,h) 128x128x64 tiles, causal skip (bit-identical) ============
__global__ __launch_bounds__(256, 2) void dots_kernel() {
    const int bh = blockIdx.z;
    const int b = bh >> 4, h = bh & 15;
    const int i0 = blockIdx.y << 7;
    const int j0 = blockIdx.x << 7;
    if (j0 > i0 + 127 + NM) return;
    __shared__ float Qs[64][132];
    __shared__ float Ks[64][132];
    const int tid = threadIdx.x;
    const int ty = tid >> 4, tx = tid & 15;
    const int lr = tid >> 4;
    const int lc = (tid & 15) << 2;
#pragma unroll
    for (int rr = 0; rr < 128; rr += 16) {
        int r = lr + rr;
        float4 q = *(const float4*)&g_Q[b][h][i0 + r][lc];
        Qs[lc + 0][r] = q.x; Qs[lc + 1][r] = q.y;
        Qs[lc + 2][r] = q.z; Qs[lc + 3][r] = q.w;
        int j = j0 + r;
        float4 kv = make_float4(0.f, 0.f, 0.f, 0.f);
        if (j < JTOT) kv = *(const float4*)&g_K[b][h][j][lc];
        Ks[lc + 0][r] = kv.x; Ks[lc + 1][r] = kv.y;
        Ks[lc + 2][r] = kv.z; Ks[lc + 3][r] = kv.w;
    }
    __syncthreads();
    float acc[8][8];
#pragma unroll
    for (int i = 0; i < 8; i++)
#pragma unroll
        for (int j = 0; j < 8; j++) acc[i][j] = 0.f;
#pragma unroll
    for (int kk = 0; kk < 64; kk++) {
        float4 a04 = *(const float4*)&Qs[kk][ty << 3];
        float4 a14 = *(const float4*)&Qs[kk][(ty << 3) + 4];
        float4 b04 = *(const float4*)&Ks[kk][tx << 3];
        float4 b14 = *(const float4*)&Ks[kk][(tx << 3) + 4];
        float av[8] = {a04.x, a04.y, a04.z, a04.w, a14.x, a14.y, a14.z, a14.w};
        float bv[8] = {b04.x, b04.y, b04.z, b04.w, b14.x, b14.y, b14.z, b14.w};
#pragma unroll
        for (int i = 0; i < 8; i++)
#pragma unroll
            for (int j = 0; j < 8; j++) acc[i][j] += av[i] * bv[j];
    }
    const float scale = 0.125f;
#pragma unroll
    for (int i = 0; i < 8; i++) {
        int irow = i0 + (ty << 3) + i;
#pragma unroll
        for (int j2 = 0; j2 < 8; j2 += 4) {
            int jcol = j0 + (tx << 3) + j2;
            if (jcol < JTOT) {
                float4 v = make_float4(acc[i][j2] * scale, acc[i][j2 + 1] * scale,
                                       acc[i][j2 + 2] * scale, acc[i][j2 + 3] * scale);
                *(float4*)&g_dots[b][h][irow][jcol] = v;
            }
        }
    }
}

// ============ fused per-row attention: 1024 threads ============
#define ATTN_SMEM_FLOATS (H*JTOT + 256 + 256 + H*64*8 + 32 + 16)
#define ATTN_SMEM_INTS   (JTOT + JTOT)
#define ATTN_SMEM_BYTES  ((ATTN_SMEM_FLOATS + ATTN_SMEM_INTS) * 4)

#define INS8(vv) do { float _v = (vv); \
    if (_v > t8[7]) { t8[7] = _v; \
        _Pragma("unroll") \
        for (int _q = 7; _q >= 1; _q--) \
            if (t8[_q] > t8[_q-1]) { float _t = t8[_q]; t8[_q] = t8[_q-1]; t8[_q-1] = _t; } \
    } } while (0)

__global__ __launch_bounds__(1024) void attn_kernel(
    const float* __restrict__ pre, const float* __restrict__ post) {
    const int i = (NSEQ - 1) - blockIdx.x;
    const int b = blockIdx.y;
    const int tid = threadIdx.x;
    extern __shared__ float sm[];
    float* s_d    = sm;
    float* s_pre  = s_d + H * JTOT;
    float* s_post = s_pre + 256;
    float* s_top  = s_post + 256;
    float* s_zred = s_top + H * 64 * 8;
    float* s_inv  = s_zred + 32;
    int* s_flag = (int*)(s_inv + 16);
    int* s_list = s_flag + JTOT;          // 16B-aligned (offsets are multiples of 16 floats)
    __shared__ int s_wsum[32];

    if (tid < 256) { s_pre[tid] = pre[tid]; s_post[tid] = post[tid]; }
    const int nv = i + NM + 1;
    __syncthreads();

    // ---- fused load + premix + flag zero: ONE COLUMN PER THREAD (all active) ----
    {
        const float* dbase = &g_dots[b][0][i][0];
        const long hstride = (long)NSEQ * JTOT;
        for (int j = tid; j < nv; j += 1024) {
            s_flag[j] = 0;
            float r[16];
#pragma unroll
            for (int h2 = 0; h2 < 16; h2++) r[h2] = dbase[h2 * hstride + j];
#pragma unroll
            for (int k = 0; k < 16; k++) {
                float a = 0.f;
#pragma unroll
                for (int h2 = 0; h2 < 16; h2++) a += r[h2] * s_pre[h2 * 16 + k];
                s_d[k * JTOT + j] = a;
            }
        }
    }
    __syncthreads();

    // ---- top-8 per row: 64 threads per row, float4 scan ----
    const int row = tid >> 6;
    const int t64 = tid & 63;
    const float* rd = s_d + row * JTOT;
    float t8[8];
#pragma unroll
    for (int q = 0; q < 8; q++) t8[q] = -FLT_MAX;
    {
        const int n4 = nv >> 2;
        for (int q = t64; q < n4; q += 64) {
            float4 v4 = *(const float4*)&rd[q << 2];
            INS8(v4.x); INS8(v4.y); INS8(v4.z); INS8(v4.w);
        }
        int tail = nv & 3;
        if (t64 < tail) INS8(rd[(n4 << 2) + t64]);
    }
    {
        float* myl = s_top + (row * 64 + t64) * 8;
#pragma unroll
        for (int q = 0; q < 8; q++) myl[q] = t8[q];
    }
    __syncthreads();
    if (t64 < 32) {
        float* A  = s_top + (row * 64 + t64) * 8;
        float* B2 = s_top + (row * 64 + t64 + 32) * 8;
        float out[8];
        int ia = 0, ib = 0;
#pragma unroll
        for (int r2 = 0; r2 < 8; r2++) {
            float va = A[ia];
            float vb = B2[ib];
            bool ta = (va >= vb);
            out[r2] = ta ? va : vb;
            ia += ta ? 1 : 0;
            ib += ta ? 0 : 1;
        }
#pragma unroll
        for (int r2 = 0; r2 < 8; r2++) A[r2] = out[r2];
    }
    __syncthreads();
    if (t64 < 32) {
#pragma unroll
        for (int L = 16; L >= 1; L >>= 1) {
            if (t64 < L) {
                float* A  = s_top + (row * 64 + t64) * 8;
                float* B2 = s_top + (row * 64 + t64 + L) * 8;
                float out[8];
                int ia = 0, ib = 0;
#pragma unroll
                for (int r2 = 0; r2 < 8; r2++) {
                    float va = A[ia];
                    float vb = B2[ib];
                    bool ta = (va >= vb);
                    out[r2] = ta ? va : vb;
                    ia += ta ? 1 : 0;
                    ib += ta ? 0 : 1;
                }
#pragma unroll
                for (int r2 = 0; r2 < 8; r2++) A[r2] = out[r2];
            }
            __syncwarp();
        }
    }
    __syncthreads();
    const float thr = s_top[row * 512 + 7];
    const float mx  = s_top[row * 512 + 0];

    // ---- exp-sum pass ----
    float psum = 0.f;
    {
        float* wrow = s_d + row * JTOT;
        const int np2 = nv >> 1;
        for (int q = t64; q < np2; q += 64) {
            int j = q << 1;
            float2 v = *(const float2*)&wrow[j];
            bool k0 = (v.x >= thr), k1 = (v.y >= thr);
            float e0 = k0 ? __expf(v.x - mx) : 0.f;
            float e1 = k1 ? __expf(v.y - mx) : 0.f;
            psum += e0; psum += e1;
            *(float2*)&wrow[j] = make_float2(e0, e1);
            if (k0) s_flag[j] = 1;
            if (k1) s_flag[j + 1] = 1;
        }
        if ((nv & 1) && t64 == 0) {
            int j = nv - 1;
            float v = wrow[j];
            if (v >= thr) { float e = __expf(v - mx); psum += e; wrow[j] = e; s_flag[j] = 1; }
            else wrow[j] = 0.f;
        }
    }
#pragma unroll
    for (int off = 16; off >= 1; off >>= 1)
        psum += __shfl_down_sync(0xffffffffu, psum, off);
    if ((tid & 31) == 0) s_zred[tid >> 5] = psum;
    __syncthreads();
    if (t64 == 0) s_inv[row] = 1.f / (s_zred[row * 2] + s_zred[row * 2 + 1]);

    // ---- survivor compaction ----
    const int lane = tid & 31;
    const int wid  = tid >> 5;
    const int CH = 3;
    int base = tid * CH;
    int end = base + CH; if (end > nv) end = nv;
    int c = 0;
    for (int j = base; j < end; j++) c += s_flag[j];
    int val = c;
#pragma unroll
    for (int off = 1; off < 32; off <<= 1) {
        int u = __shfl_up_sync(0xffffffffu, val, off);
        if (lane >= off) val += u;
    }
    if (lane == 31) s_wsum[wid] = val;
    __syncthreads();
    if (tid < 32) {
        int v = s_wsum[tid];
#pragma unroll
        for (int off = 1; off < 32; off <<= 1) {
            int u = __shfl_up_sync(0xffffffffu, v, off);
            if (tid >= off) v += u;
        }
        s_wsum[tid] = v;
    }
    __syncthreads();
    {
        int pos = (wid > 0 ? s_wsum[wid - 1] : 0) + (val - c);
        for (int j = base; j < end; j++)
            if (s_flag[j]) s_list[pos++] = j;
    }
    const int cnt = s_wsum[31];
    __syncthreads();

    // ---- post-mix at survivor columns (inv folded in) ----
    for (int sI = tid; sI < cnt; sI += 1024) {
        int j = s_list[sI];
        float a[16];
#pragma unroll
        for (int h2 = 0; h2 < 16; h2++) a[h2] = s_d[h2 * JTOT + j] * s_inv[h2];
#pragma unroll
        for (int k = 0; k < 16; k++) {
            float acc2 = 0.f;
#pragma unroll
            for (int h2 = 0; h2 < 16; h2++) acc2 += a[h2] * s_post[h2 * 16 + k];
            s_d[k * JTOT + j] = acc2;
        }
    }
    __syncthreads();

    // ---- sparse attn2 @ V: 64 threads per head, unrolled x4 for MLP ----
    const int kk2 = tid >> 6;   // head
    const int d = tid & 63;     // dim
    float acc = 0.f;
    const float* Vb = &g_V[b][kk2][0][0];
    const float* wr = s_d + kk2 * JTOT;
    int s2 = 0;
    for (; s2 + 3 < cnt; s2 += 4) {
        int4 j4 = *(const int4*)&s_list[s2];
        float w0 = wr[j4.x], w1 = wr[j4.y], w2 = wr[j4.z], w3 = wr[j4.w];
        float v0 = Vb[j4.x * 64 + d];
        float v1 = Vb[j4.y * 64 + d];
        float v2 = Vb[j4.z * 64 + d];
        float v3 = Vb[j4.w * 64 + d];
        acc += w0 * v0 + w1 * v1;
        acc += w2 * v2 + w3 * v3;
    }
    for (; s2 < cnt; s2++) {
        int ja = s_list[s2];
        acc += wr[ja] * Vb[ja * 64 + d];
    }
    bf16 hx, lx;
    bsplit2(acc, hx, lx);
    long off2 = (long)(b * NSEQ + i) * DIM + kk2 * 64 + d;
    g_ctxh[off2] = hx;
    g_ctxl[off2] = lx;
}

// ============ output projection: bf16x3 wmma + bias (linear path) ============
__global__ __launch_bounds__(256) void out_wmma(const float* __restrict__ bo,
                                                float* __restrict__ outp) {
    __shared__ float sEpi[128 * 72];
    bf16* sAh = (bf16*)sEpi;
    bf16* sAl = sAh + 128 * 40;
    bf16* sBh = sAl + 128 * 40;
    bf16* sBl = sBh + 32 * 72;
    const int m0 = blockIdx.y << 7;
    const int n0 = blockIdx.x << 6;
    const int tid = threadIdx.x;
    const int w = tid >> 5;
    const int wm = w >> 1, wn = w & 1;

    wmma::fragment<wmma::accumulator, 16, 16, 16, float> acc[2][2];
#pragma unroll
    for (int i = 0; i < 2; i++)
#pragma unroll
        for (int j = 0; j < 2; j++) wmma::fill_fragment(acc[i][j], 0.f);

    for (int k0 = 0; k0 < DIM; k0 += 32) {
        __syncthreads();
#pragma unroll
        for (int it = 0; it < 4; it++) {
            int idx = tid + it * 256;
            int r = idx >> 3, c = (idx & 7) << 2;
            long g = (long)(m0 + r) * DIM + k0 + c;
            *(uint2*)&sAh[r * 40 + c] = *(const uint2*)&g_ctxh[g];
            *(uint2*)&sAl[r * 40 + c] = *(const uint2*)&g_ctxl[g];
        }
#pragma unroll
        for (int it = 0; it < 2; it++) {
            int idx = tid + it * 256;
            int r = idx >> 4, c = (idx & 15) << 2;
            long g = (long)(k0 + r) * DIM + n0 + c;
            *(uint2*)&sBh[r * 72 + c] = *(const uint2*)&g_Woh[g];
            *(uint2*)&sBl[r * 72 + c] = *(const uint2*)&g_Wol[g];
        }
        __syncthreads();
#pragma unroll
        for (int ks = 0; ks < 2; ks++) {
            int k = ks << 4;
            wmma::fragment<wmma::matrix_a, 16, 16, 16, bf16, wmma::row_major> ah[2], al[2];
            wmma::fragment<wmma::matrix_b, 16, 16, 16, bf16, wmma::row_major> bh[2], bl[2];
#pragma unroll
            for (int fm = 0; fm < 2; fm++) {
                wmma::load_matrix_sync(ah[fm], &sAh[(wm * 32 + fm * 16) * 40 + k], 40);
                wmma::load_matrix_sync(al[fm], &sAl[(wm * 32 + fm * 16) * 40 + k], 40);
            }
#pragma unroll
            for (int fn = 0; fn < 2; fn++) {
                wmma::load_matrix_sync(bh[fn], &sBh[k * 72 + wn * 32 + fn * 16], 72);
                wmma::load_matrix_sync(bl[fn], &sBl[k * 72 + wn * 32 + fn * 16], 72);
            }
#pragma unroll
            for (int fm = 0; fm < 2; fm++)
#pragma unroll
                for (int fn = 0; fn < 2; fn++) {
                    wmma::mma_sync(acc[fm][fn], ah[fm], bl[fn], acc[fm][fn]);
                    wmma::mma_sync(acc[fm][fn], al[fm], bh[fn], acc[fm][fn]);
                    wmma::mma_sync(acc[fm][fn], ah[fm], bh[fn], acc[fm][fn]);
                }
        }
    }
    __syncthreads();
#pragma unroll
    for (int fm = 0; fm < 2; fm++)
#pragma unroll
        for (int fn = 0; fn < 2; fn++)
            wmma::store_matrix_sync(&sEpi[(wm * 32 + fm * 16) * 72 + wn * 32 + fn * 16],
                                    acc[fm][fn], 72, wmma::mem_row_major);
    __syncthreads();
#pragma unroll
    for (int it = 0; it < 8; it++) {
        int idx = tid + it * 256;
        int r = idx >> 4, c = (idx & 15) << 2;
        float4 v = *(const float4*)&sEpi[r * 72 + c];
        float4 bias = *(const float4*)&bo[n0 + c];
        v.x += bias.x; v.y += bias.y; v.z += bias.z; v.w += bias.w;
        *(float4*)&outp[(m0 + r) * DIM + n0 + c] = v;
    }
}

// ---------------- launch ----------------
extern "C" void kernel_launch(void* const* d_in, const int* in_sizes, int n_in,
                              void* d_out, int out_size) {
    const float* x    = (const float*)d_in[0];
    const float* Wq   = (const float*)d_in[1];
    const float* Wk   = (const float*)d_in[2];
    const float* Wv   = (const float*)d_in[3];
    const float* pre  = (const float*)d_in[4];
    const float* post = (const float*)d_in[5];
    const float* mk   = (const float*)d_in[6];
    const float* mv   = (const float*)d_in[7];
    const float* Wo   = (const float*)d_in[8];
    const float* bo   = (const float*)d_in[9];
    float* out = (float*)d_out;

    cudaFuncSetAttribute(attn_kernel, cudaFuncAttributeMaxDynamicSharedMemorySize, ATTN_SMEM_BYTES);

    bf16 *xh, *xl, *wvh, *wvl, *woh, *wol;
    cudaGetSymbolAddress((void**)&xh,  g_xh);  cudaGetSymbolAddress((void**)&xl,  g_xl);
    cudaGetSymbolAddress((void**)&wvh, g_Wvh); cudaGetSymbolAddress((void**)&wvl, g_Wvl);
    cudaGetSymbolAddress((void**)&woh, g_Woh); cudaGetSymbolAddress((void**)&wol, g_Wol);

    memfill_kernel<<<(BATCH * H * NM * DH + 255) / 256, 256>>>(mk, mv);
    split2<<<(MROWS * DIM + 255) / 256, 256>>>(x,  xh,  xl,  MROWS * DIM);
    split2<<<(DIM * DIM + 255) / 256, 256>>>(Wv, wvh, wvl, DIM * DIM);
    split2<<<(DIM * DIM + 255) / 256, 256>>>(Wo, woh, wol, DIM * DIM);

    gemm_qkv_kernel<<<dim3(DIM / 128, MROWS / 128, 2), 256>>>(x, Wq, Wk, Wv);  // Q,K fp32
    v_wmma<<<dim3(DIM / 64, MROWS / 128), 256>>>();                            // V bf16x3
    dots_kernel<<<dim3((JTOT + 127) / 128, NSEQ / 128, BATCH * H), 256>>>();
    attn_kernel<<<dim3(NSEQ, BATCH), 1024, ATTN_SMEM_BYTES>>>(pre, post);
    out_wmma<<<dim3(DIM / 64, MROWS / 128), 256>>>(bo, out);                   // out bf16x3
}

// round 13
// speedup vs baseline: 1.0734x; 1.0734x over previous
#include <cuda_runtime.h>
#include <cuda_bf16.h>
#include <mma.h>
#include <float.h>
#include <math.h>

using namespace nvcuda;
typedef __nv_bfloat16 bf16;

#define BATCH 2
#define NSEQ  2048
#define DIM   1024
#define H     16
#define DH    64
#define NM    16
#define JTOT  2064          // NM + NSEQ
#define MROWS (BATCH*NSEQ)  // 4096

// ---------------- global scratch ----------------
__device__ float g_Q[BATCH][H][NSEQ][DH];
__device__ float g_K[BATCH][H][JTOT][DH];
__device__ float g_V[BATCH][H][JTOT][DH];
__device__ float g_dots[BATCH][H][NSEQ][JTOT];
__device__ bf16  g_xh[MROWS*DIM],  g_xl[MROWS*DIM];
__device__ bf16  g_Wvh[DIM*DIM],   g_Wvl[DIM*DIM];
__device__ bf16  g_Woh[DIM*DIM],   g_Wol[DIM*DIM];
__device__ bf16  g_ctxh[MROWS*DIM], g_ctxl[MROWS*DIM];

__device__ __forceinline__ void bsplit2(float v, bf16& h, bf16& l) {
    h = __float2bfloat16(v);
    l = __float2bfloat16(v - __bfloat162float(h));
}

// ---------------- fill mem_k / mem_v into K/V prefix ----------------
__global__ void memfill_kernel(const float* __restrict__ mk, const float* __restrict__ mv) {
    int idx = blockIdx.x * 256 + threadIdx.x;
    if (idx >= BATCH * H * NM * DH) return;
    int d = idx & 63;
    int j = (idx >> 6) & 15;
    int h = (idx >> 10) & 15;
    int b = idx >> 14;
    g_K[b][h][j][d] = mk[(h * NM + j) * DH + d];
    g_V[b][h][j][d] = mv[(h * NM + j) * DH + d];
}

// ---------------- bf16 hi/lo split, 4 elems per thread ----------------
__global__ void split2v(const float* __restrict__ s, bf16* __restrict__ h,
                        bf16* __restrict__ l, int n4) {
    int i = blockIdx.x * 256 + threadIdx.x;
    if (i >= n4) return;
    float4 v = *(const float4*)&s[i << 2];
    bf16 h0, l0, h1, l1, h2, l2, h3, l3;
    bsplit2(v.x, h0, l0); bsplit2(v.y, h1, l1);
    bsplit2(v.z, h2, l2); bsplit2(v.w, h3, l3);
    __nv_bfloat162 hp0; hp0.x = h0; hp0.y = h1;
    __nv_bfloat162 hp1; hp1.x = h2; hp1.y = h3;
    __nv_bfloat162 lp0; lp0.x = l0; lp0.y = l1;
    __nv_bfloat162 lp1; lp1.x = l2; lp1.y = l3;
    uint2 hu, lu;
    hu.x = *(unsigned*)&hp0; hu.y = *(unsigned*)&hp1;
    lu.x = *(unsigned*)&lp0; lu.y = *(unsigned*)&lp1;
    *(uint2*)&h[i << 2] = hu;
    *(uint2*)&l[i << 2] = lu;
}

// ============ 128x128x16 fp32 GEMM (Q,K only — bit-identical path) ============
__global__ __launch_bounds__(256, 2) void gemm_qkv_kernel(
    const float* __restrict__ x, const float* __restrict__ Wq,
    const float* __restrict__ Wk, const float* __restrict__ Wv) {
    const int z = blockIdx.z;
    const float* W = (z == 0) ? Wq : (z == 1) ? Wk : Wv;
    __shared__ float As[2][16][132];
    __shared__ float Bs[2][16][132];
    const int m0 = blockIdx.y << 7;
    const int n0 = blockIdx.x << 7;
    const int tid = threadIdx.x;
    const int ty = tid >> 4, tx = tid & 15;
    const int arow = tid >> 2, acol = (tid & 3) << 2;
    const int brow = tid >> 5, bcol = (tid & 31) << 2;
    float acc[8][8];
#pragma unroll
    for (int i = 0; i < 8; i++)
#pragma unroll
        for (int j = 0; j < 8; j++) acc[i][j] = 0.f;

    {
        float4 a0 = *(const float4*)&x[(m0 + arow) * DIM + acol];
        float4 a1 = *(const float4*)&x[(m0 + arow + 64) * DIM + acol];
        float4 b0 = *(const float4*)&W[brow * DIM + n0 + bcol];
        float4 b1 = *(const float4*)&W[(brow + 8) * DIM + n0 + bcol];
        As[0][acol + 0][arow] = a0.x; As[0][acol + 1][arow] = a0.y;
        As[0][acol + 2][arow] = a0.z; As[0][acol + 3][arow] = a0.w;
        As[0][acol + 0][arow + 64] = a1.x; As[0][acol + 1][arow + 64] = a1.y;
        As[0][acol + 2][arow + 64] = a1.z; As[0][acol + 3][arow + 64] = a1.w;
        *(float4*)&Bs[0][brow][bcol] = b0;
        *(float4*)&Bs[0][brow + 8][bcol] = b1;
    }
    __syncthreads();

    int cur = 0;
    for (int k0 = 0; k0 < DIM; k0 += 16) {
        const int nxt = k0 + 16;
        float4 na0, na1, nb0, nb1;
        if (nxt < DIM) {
            na0 = *(const float4*)&x[(m0 + arow) * DIM + nxt + acol];
            na1 = *(const float4*)&x[(m0 + arow + 64) * DIM + nxt + acol];
            nb0 = *(const float4*)&W[(nxt + brow) * DIM + n0 + bcol];
            nb1 = *(const float4*)&W[(nxt + brow + 8) * DIM + n0 + bcol];
        }
#pragma unroll
        for (int kk = 0; kk < 16; kk++) {
            float4 a04 = *(const float4*)&As[cur][kk][ty << 3];
            float4 a14 = *(const float4*)&As[cur][kk][(ty << 3) + 4];
            float4 b04 = *(const float4*)&Bs[cur][kk][tx << 3];
            float4 b14 = *(const float4*)&Bs[cur][kk][(tx << 3) + 4];
            float av[8] = {a04.x, a04.y, a04.z, a04.w, a14.x, a14.y, a14.z, a14.w};
            float bv[8] = {b04.x, b04.y, b04.z, b04.w, b14.x, b14.y, b14.z, b14.w};
#pragma unroll
            for (int i = 0; i < 8; i++)
#pragma unroll
                for (int j = 0; j < 8; j++) acc[i][j] += av[i] * bv[j];
        }
        if (nxt < DIM) {
            const int nb = cur ^ 1;
            As[nb][acol + 0][arow] = na0.x; As[nb][acol + 1][arow] = na0.y;
            As[nb][acol + 2][arow] = na0.z; As[nb][acol + 3][arow] = na0.w;
            As[nb][acol + 0][arow + 64] = na1.x; As[nb][acol + 1][arow + 64] = na1.y;
            As[nb][acol + 2][arow + 64] = na1.z; As[nb][acol + 3][arow + 64] = na1.w;
            *(float4*)&Bs[nb][brow][bcol] = nb0;
            *(float4*)&Bs[nb][brow + 8][bcol] = nb1;
            __syncthreads();
            cur = nb;
        }
    }
#pragma unroll
    for (int i = 0; i < 8; i++) {
        int m = m0 + (ty << 3) + i;
        int b = m >> 11;
        int irow = m & 2047;
#pragma unroll
        for (int j2 = 0; j2 < 8; j2 += 4) {
            int c = n0 + (tx << 3) + j2;
            int h = c >> 6;
            int d = c & 63;
            float4 v = make_float4(acc[i][j2], acc[i][j2 + 1], acc[i][j2 + 2], acc[i][j2 + 3]);
            if (z == 0)      *(float4*)&g_Q[b][h][irow][d] = v;
            else if (z == 1) *(float4*)&g_K[b][h][NM + irow][d] = v;
            else             *(float4*)&g_V[b][h][NM + irow][d] = v;
        }
    }
}

// ============ V projection: bf16x3 wmma (linear path) ============
__global__ __launch_bounds__(256) void v_wmma() {
    __shared__ bf16 sAh[128 * 40], sAl[128 * 40];
    __shared__ bf16 sBh[32 * 72],  sBl[32 * 72];
    const int m0 = blockIdx.y << 7;
    const int n0 = blockIdx.x << 6;
    const int tid = threadIdx.x;
    const int w = tid >> 5;
    const int wm = w >> 1, wn = w & 1;

    wmma::fragment<wmma::accumulator, 16, 16, 16, float> acc[2][2];
#pragma unroll
    for (int i = 0; i < 2; i++)
#pragma unroll
        for (int j = 0; j < 2; j++) wmma::fill_fragment(acc[i][j], 0.f);

    for (int k0 = 0; k0 < DIM; k0 += 32) {
        __syncthreads();
#pragma unroll
        for (int it = 0; it < 4; it++) {
            int idx = tid + it * 256;
            int r = idx >> 3, c = (idx & 7) << 2;
            long g = (long)(m0 + r) * DIM + k0 + c;
            *(uint2*)&sAh[r * 40 + c] = *(const uint2*)&g_xh[g];
            *(uint2*)&sAl[r * 40 + c] = *(const uint2*)&g_xl[g];
        }
#pragma unroll
        for (int it = 0; it < 2; it++) {
            int idx = tid + it * 256;
            int r = idx >> 4, c = (idx & 15) << 2;
            long g = (long)(k0 + r) * DIM + n0 + c;
            *(uint2*)&sBh[r * 72 + c] = *(const uint2*)&g_Wvh[g];
            *(uint2*)&sBl[r * 72 + c] = *(const uint2*)&g_Wvl[g];
        }
        __syncthreads();
#pragma unroll
        for (int ks = 0; ks < 2; ks++) {
            int k = ks << 4;
            wmma::fragment<wmma::matrix_a, 16, 16, 16, bf16, wmma::row_major> ah[2], al[2];
            wmma::fragment<wmma::matrix_b, 16, 16, 16, bf16, wmma::row_major> bh[2], bl[2];
#pragma unroll
            for (int fm = 0; fm < 2; fm++) {
                wmma::load_matrix_sync(ah[fm], &sAh[(wm * 32 + fm * 16) * 40 + k], 40);
                wmma::load_matrix_sync(al[fm], &sAl[(wm * 32 + fm * 16) * 40 + k], 40);
            }
#pragma unroll
            for (int fn = 0; fn < 2; fn++) {
                wmma::load_matrix_sync(bh[fn], &sBh[k * 72 + wn * 32 + fn * 16], 72);
                wmma::load_matrix_sync(bl[fn], &sBl[k * 72 + wn * 32 + fn * 16], 72);
            }
#pragma unroll
            for (int fm = 0; fm < 2; fm++)
#pragma unroll
                for (int fn = 0; fn < 2; fn++) {
                    wmma::mma_sync(acc[fm][fn], ah[fm], bl[fn], acc[fm][fn]);
                    wmma::mma_sync(acc[fm][fn], al[fm], bh[fn], acc[fm][fn]);
                    wmma::mma_sync(acc[fm][fn], ah[fm], bh[fn], acc[fm][fn]);
                }
        }
    }
    const int h = n0 >> 6;
#pragma unroll
    for (int fm = 0; fm < 2; fm++) {
        int m = m0 + wm * 32 + fm * 16;
        int b = m >> 11;
        int irow = m & 2047;
#pragma unroll
        for (int fn = 0; fn < 2; fn++) {
            int d = wn * 32 + fn * 16;
            wmma::store_matrix_sync(&g_V[b][h][NM + irow][d], acc[fm][fn], DH, wmma::mem_row_major);
        }
    }
}

// ============ dots: per (b,h) 128x128x64 tiles, causal skip (bit-identical) ============
__global__ __launch_bounds__(256, 2) void dots_kernel() {
    const int bh = blockIdx.z;
    const int b = bh >> 4, h = bh & 15;
    const int i0 = blockIdx.y << 7;
    const int j0 = blockIdx.x << 7;
    if (j0 > i0 + 127 + NM) return;
    __shared__ float Qs[64][132];
    __shared__ float Ks[64][132];
    const int tid = threadIdx.x;
    const int ty = tid >> 4, tx = tid & 15;
    const int lr = tid >> 4;
    const int lc = (tid & 15) << 2;
#pragma unroll
    for (int rr = 0; rr < 128; rr += 16) {
        int r = lr + rr;
        float4 q = *(const float4*)&g_Q[b][h][i0 + r][lc];
        Qs[lc + 0][r] = q.x; Qs[lc + 1][r] = q.y;
        Qs[lc + 2][r] = q.z; Qs[lc + 3][r] = q.w;
        int j = j0 + r;
        float4 kv = make_float4(0.f, 0.f, 0.f, 0.f);
        if (j < JTOT) kv = *(const float4*)&g_K[b][h][j][lc];
        Ks[lc + 0][r] = kv.x; Ks[lc + 1][r] = kv.y;
        Ks[lc + 2][r] = kv.z; Ks[lc + 3][r] = kv.w;
    }
    __syncthreads();
    float acc[8][8];
#pragma unroll
    for (int i = 0; i < 8; i++)
#pragma unroll
        for (int j = 0; j < 8; j++) acc[i][j] = 0.f;
#pragma unroll
    for (int kk = 0; kk < 64; kk++) {
        float4 a04 = *(const float4*)&Qs[kk][ty << 3];
        float4 a14 = *(const float4*)&Qs[kk][(ty << 3) + 4];
        float4 b04 = *(const float4*)&Ks[kk][tx << 3];
        float4 b14 = *(const float4*)&Ks[kk][(tx << 3) + 4];
        float av[8] = {a04.x, a04.y, a04.z, a04.w, a14.x, a14.y, a14.z, a14.w};
        float bv[8] = {b04.x, b04.y, b04.z, b04.w, b14.x, b14.y, b14.z, b14.w};
#pragma unroll
        for (int i = 0; i < 8; i++)
#pragma unroll
            for (int j = 0; j < 8; j++) acc[i][j] += av[i] * bv[j];
    }
    const float scale = 0.125f;
#pragma unroll
    for (int i = 0; i < 8; i++) {
        int irow = i0 + (ty << 3) + i;
#pragma unroll
        for (int j2 = 0; j2 < 8; j2 += 4) {
            int jcol = j0 + (tx << 3) + j2;
            if (jcol < JTOT) {
                float4 v = make_float4(acc[i][j2] * scale, acc[i][j2 + 1] * scale,
                                       acc[i][j2 + 2] * scale, acc[i][j2 + 3] * scale);
                *(float4*)&g_dots[b][h][irow][jcol] = v;
            }
        }
    }
}

// ============ fused per-row attention: 1024 threads (R11 structure) ============
#define ATTN_SMEM_FLOATS (H*JTOT + 256 + 256 + H*64*8 + 32 + 16)
#define ATTN_SMEM_INTS   (JTOT + JTOT)
#define ATTN_SMEM_BYTES  ((ATTN_SMEM_FLOATS + ATTN_SMEM_INTS) * 4)

#define INS8(vv) do { float _v = (vv); \
    if (_v > t8[7]) { t8[7] = _v; \
        _Pragma("unroll") \
        for (int _q = 7; _q >= 1; _q--) \
            if (t8[_q] > t8[_q-1]) { float _t = t8[_q]; t8[_q] = t8[_q-1]; t8[_q-1] = _t; } \
    } } while (0)

__global__ __launch_bounds__(1024) void attn_kernel(
    const float* __restrict__ pre, const float* __restrict__ post) {
    const int i = (NSEQ - 1) - blockIdx.x;
    const int b = blockIdx.y;
    const int tid = threadIdx.x;
    extern __shared__ float sm[];
    float* s_d    = sm;
    float* s_pre  = s_d + H * JTOT;
    float* s_post = s_pre + 256;
    float* s_top  = s_post + 256;
    float* s_zred = s_top + H * 64 * 8;
    float* s_inv  = s_zred + 32;
    int* s_flag = (int*)(s_inv + 16);
    int* s_list = s_flag + JTOT;
    __shared__ int s_wsum[32];

    if (tid < 256) { s_pre[tid] = pre[tid]; s_post[tid] = post[tid]; }
    const int nv = i + NM + 1;
    __syncthreads();

    // ---- fused load + premix + flag zero (float2 per thread — R11 layout) ----
    {
        const float* dbase = &g_dots[b][0][i][0];
        const long hstride = (long)NSEQ * JTOT;
        const int npair = (nv + 1) >> 1;
        for (int p = tid; p < npair; p += 1024) {
            int j = p << 1;
            s_flag[j] = 0;
            if (j + 1 < nv) {
                s_flag[j + 1] = 0;
                float2 r[16];
#pragma unroll
                for (int h2 = 0; h2 < 16; h2++)
                    r[h2] = *(const float2*)&dbase[h2 * hstride + j];
#pragma unroll
                for (int k = 0; k < 16; k++) {
                    float a0 = 0.f, a1 = 0.f;
#pragma unroll
                    for (int h2 = 0; h2 < 16; h2++) {
                        float w = s_pre[h2 * 16 + k];
                        a0 += r[h2].x * w;
                        a1 += r[h2].y * w;
                    }
                    *(float2*)&s_d[k * JTOT + j] = make_float2(a0, a1);
                }
            } else {
                float r1[16];
#pragma unroll
                for (int h2 = 0; h2 < 16; h2++) r1[h2] = dbase[h2 * hstride + j];
#pragma unroll
                for (int k = 0; k < 16; k++) {
                    float a = 0.f;
#pragma unroll
                    for (int h2 = 0; h2 < 16; h2++) a += r1[h2] * s_pre[h2 * 16 + k];
                    s_d[k * JTOT + j] = a;
                }
            }
        }
    }
    __syncthreads();

    // ---- top-8 per row: 64 threads per row, float4 scan ----
    const int row = tid >> 6;
    const int t64 = tid & 63;
    const float* rd = s_d + row * JTOT;
    float t8[8];
#pragma unroll
    for (int q = 0; q < 8; q++) t8[q] = -FLT_MAX;
    {
        const int n4 = nv >> 2;
        for (int q = t64; q < n4; q += 64) {
            float4 v4 = *(const float4*)&rd[q << 2];
            INS8(v4.x); INS8(v4.y); INS8(v4.z); INS8(v4.w);
        }
        int tail = nv & 3;
        if (t64 < tail) INS8(rd[(n4 << 2) + t64]);
    }
    {
        float* myl = s_top + (row * 64 + t64) * 8;
#pragma unroll
        for (int q = 0; q < 8; q++) myl[q] = t8[q];
    }
    __syncthreads();
    if (t64 < 32) {
        float* A  = s_top + (row * 64 + t64) * 8;
        float* B2 = s_top + (row * 64 + t64 + 32) * 8;
        float out[8];
        int ia = 0, ib = 0;
#pragma unroll
        for (int r2 = 0; r2 < 8; r2++) {
            float va = A[ia];
            float vb = B2[ib];
            bool ta = (va >= vb);
            out[r2] = ta ? va : vb;
            ia += ta ? 1 : 0;
            ib += ta ? 0 : 1;
        }
#pragma unroll
        for (int r2 = 0; r2 < 8; r2++) A[r2] = out[r2];
    }
    __syncthreads();
    if (t64 < 32) {
#pragma unroll
        for (int L = 16; L >= 1; L >>= 1) {
            if (t64 < L) {
                float* A  = s_top + (row * 64 + t64) * 8;
                float* B2 = s_top + (row * 64 + t64 + L) * 8;
                float out[8];
                int ia = 0, ib = 0;
#pragma unroll
                for (int r2 = 0; r2 < 8; r2++) {
                    float va = A[ia];
                    float vb = B2[ib];
                    bool ta = (va >= vb);
                    out[r2] = ta ? va : vb;
                    ia += ta ? 1 : 0;
                    ib += ta ? 0 : 1;
                }
#pragma unroll
                for (int r2 = 0; r2 < 8; r2++) A[r2] = out[r2];
            }
            __syncwarp();
        }
    }
    __syncthreads();
    const float thr = s_top[row * 512 + 7];
    const float mx  = s_top[row * 512 + 0];

    // ---- exp-sum pass ----
    float psum = 0.f;
    {
        float* wrow = s_d + row * JTOT;
        const int np2 = nv >> 1;
        for (int q = t64; q < np2; q += 64) {
            int j = q << 1;
            float2 v = *(const float2*)&wrow[j];
            bool k0 = (v.x >= thr), k1 = (v.y >= thr);
            float e0 = k0 ? __expf(v.x - mx) : 0.f;
            float e1 = k1 ? __expf(v.y - mx) : 0.f;
            psum += e0; psum += e1;
            *(float2*)&wrow[j] = make_float2(e0, e1);
            if (k0) s_flag[j] = 1;
            if (k1) s_flag[j + 1] = 1;
        }
        if ((nv & 1) && t64 == 0) {
            int j = nv - 1;
            float v = wrow[j];
            if (v >= thr) { float e = __expf(v - mx); psum += e; wrow[j] = e; s_flag[j] = 1; }
            else wrow[j] = 0.f;
        }
    }
#pragma unroll
    for (int off = 16; off >= 1; off >>= 1)
        psum += __shfl_down_sync(0xffffffffu, psum, off);
    if ((tid & 31) == 0) s_zred[tid >> 5] = psum;
    __syncthreads();
    if (t64 == 0) s_inv[row] = 1.f / (s_zred[row * 2] + s_zred[row * 2 + 1]);

    // ---- survivor compaction ----
    const int lane = tid & 31;
    const int wid  = tid >> 5;
    const int CH = 3;
    int base = tid * CH;
    int end = base + CH; if (end > nv) end = nv;
    int c = 0;
    for (int j = base; j < end; j++) c += s_flag[j];
    int val = c;
#pragma unroll
    for (int off = 1; off < 32; off <<= 1) {
        int u = __shfl_up_sync(0xffffffffu, val, off);
        if (lane >= off) val += u;
    }
    if (lane == 31) s_wsum[wid] = val;
    __syncthreads();
    if (tid < 32) {
        int v = s_wsum[tid];
#pragma unroll
        for (int off = 1; off < 32; off <<= 1) {
            int u = __shfl_up_sync(0xffffffffu, v, off);
            if (tid >= off) v += u;
        }
        s_wsum[tid] = v;
    }
    __syncthreads();
    {
        int pos = (wid > 0 ? s_wsum[wid - 1] : 0) + (val - c);
        for (int j = base; j < end; j++)
            if (s_flag[j]) s_list[pos++] = j;
    }
    const int cnt = s_wsum[31];
    __syncthreads();

    // ---- post-mix at survivor columns (inv folded in) ----
    for (int sI = tid; sI < cnt; sI += 1024) {
        int j = s_list[sI];
        float a[16];
#pragma unroll
        for (int h2 = 0; h2 < 16; h2++) a[h2] = s_d[h2 * JTOT + j] * s_inv[h2];
#pragma unroll
        for (int k = 0; k < 16; k++) {
            float acc2 = 0.f;
#pragma unroll
            for (int h2 = 0; h2 < 16; h2++) acc2 += a[h2] * s_post[h2 * 16 + k];
            s_d[k * JTOT + j] = acc2;
        }
    }
    __syncthreads();

    // ---- sparse attn2 @ V: 64 threads per head, unrolled x4 for MLP ----
    const int kk2 = tid >> 6;   // head
    const int d = tid & 63;     // dim
    float acc = 0.f;
    const float* Vb = &g_V[b][kk2][0][0];
    const float* wr = s_d + kk2 * JTOT;
    int s2 = 0;
    for (; s2 + 3 < cnt; s2 += 4) {
        int4 j4 = *(const int4*)&s_list[s2];
        float w0 = wr[j4.x], w1 = wr[j4.y], w2 = wr[j4.z], w3 = wr[j4.w];
        float v0 = Vb[j4.x * 64 + d];
        float v1 = Vb[j4.y * 64 + d];
        float v2 = Vb[j4.z * 64 + d];
        float v3 = Vb[j4.w * 64 + d];
        acc += w0 * v0 + w1 * v1;
        acc += w2 * v2 + w3 * v3;
    }
    for (; s2 < cnt; s2++) {
        int ja = s_list[s2];
        acc += wr[ja] * Vb[ja * 64 + d];
    }
    bf16 hx, lx;
    bsplit2(acc, hx, lx);
    long off2 = (long)(b * NSEQ + i) * DIM + kk2 * 64 + d;
    g_ctxh[off2] = hx;
    g_ctxl[off2] = lx;
}

// ============ output projection: bf16x3 wmma + bias (linear path) ============
__global__ __launch_bounds__(256) void out_wmma(const float* __restrict__ bo,
                                                float* __restrict__ outp) {
    __shared__ float sEpi[128 * 72];
    bf16* sAh = (bf16*)sEpi;
    bf16* sAl = sAh + 128 * 40;
    bf16* sBh = sAl + 128 * 40;
    bf16* sBl = sBh + 32 * 72;
    const int m0 = blockIdx.y << 7;
    const int n0 = blockIdx.x << 6;
    const int tid = threadIdx.x;
    const int w = tid >> 5;
    const int wm = w >> 1, wn = w & 1;

    wmma::fragment<wmma::accumulator, 16, 16, 16, float> acc[2][2];
#pragma unroll
    for (int i = 0; i < 2; i++)
#pragma unroll
        for (int j = 0; j < 2; j++) wmma::fill_fragment(acc[i][j], 0.f);

    for (int k0 = 0; k0 < DIM; k0 += 32) {
        __syncthreads();
#pragma unroll
        for (int it = 0; it < 4; it++) {
            int idx = tid + it * 256;
            int r = idx >> 3, c = (idx & 7) << 2;
            long g = (long)(m0 + r) * DIM + k0 + c;
            *(uint2*)&sAh[r * 40 + c] = *(const uint2*)&g_ctxh[g];
            *(uint2*)&sAl[r * 40 + c] = *(const uint2*)&g_ctxl[g];
        }
#pragma unroll
        for (int it = 0; it < 2; it++) {
            int idx = tid + it * 256;
            int r = idx >> 4, c = (idx & 15) << 2;
            long g = (long)(k0 + r) * DIM + n0 + c;
            *(uint2*)&sBh[r * 72 + c] = *(const uint2*)&g_Woh[g];
            *(uint2*)&sBl[r * 72 + c] = *(const uint2*)&g_Wol[g];
        }
        __syncthreads();
#pragma unroll
        for (int ks = 0; ks < 2; ks++) {
            int k = ks << 4;
            wmma::fragment<wmma::matrix_a, 16, 16, 16, bf16, wmma::row_major> ah[2], al[2];
            wmma::fragment<wmma::matrix_b, 16, 16, 16, bf16, wmma::row_major> bh[2], bl[2];
#pragma unroll
            for (int fm = 0; fm < 2; fm++) {
                wmma::load_matrix_sync(ah[fm], &sAh[(wm * 32 + fm * 16) * 40 + k], 40);
                wmma::load_matrix_sync(al[fm], &sAl[(wm * 32 + fm * 16) * 40 + k], 40);
            }
#pragma unroll
            for (int fn = 0; fn < 2; fn++) {
                wmma::load_matrix_sync(bh[fn], &sBh[k * 72 + wn * 32 + fn * 16], 72);
                wmma::load_matrix_sync(bl[fn], &sBl[k * 72 + wn * 32 + fn * 16], 72);
            }
#pragma unroll
            for (int fm = 0; fm < 2; fm++)
#pragma unroll
                for (int fn = 0; fn < 2; fn++) {
                    wmma::mma_sync(acc[fm][fn], ah[fm], bl[fn], acc[fm][fn]);
                    wmma::mma_sync(acc[fm][fn], al[fm], bh[fn], acc[fm][fn]);
                    wmma::mma_sync(acc[fm][fn], ah[fm], bh[fn], acc[fm][fn]);
                }
        }
    }
    __syncthreads();
#pragma unroll
    for (int fm = 0; fm < 2; fm++)
#pragma unroll
        for (int fn = 0; fn < 2; fn++)
            wmma::store_matrix_sync(&sEpi[(wm * 32 + fm * 16) * 72 + wn * 32 + fn * 16],
                                    acc[fm][fn], 72, wmma::mem_row_major);
    __syncthreads();
#pragma unroll
    for (int it = 0; it < 8; it++) {
        int idx = tid + it * 256;
        int r = idx >> 4, c = (idx & 15) << 2;
        float4 v = *(const float4*)&sEpi[r * 72 + c];
        float4 bias = *(const float4*)&bo[n0 + c];
        v.x += bias.x; v.y += bias.y; v.z += bias.z; v.w += bias.w;
        *(float4*)&outp[(m0 + r) * DIM + n0 + c] = v;
    }
}

// ---------------- launch ----------------
extern "C" void kernel_launch(void* const* d_in, const int* in_sizes, int n_in,
                              void* d_out, int out_size) {
    const float* x    = (const float*)d_in[0];
    const float* Wq   = (const float*)d_in[1];
    const float* Wk   = (const float*)d_in[2];
    const float* Wv   = (const float*)d_in[3];
    const float* pre  = (const float*)d_in[4];
    const float* post = (const float*)d_in[5];
    const float* mk   = (const float*)d_in[6];
    const float* mv   = (const float*)d_in[7];
    const float* Wo   = (const float*)d_in[8];
    const float* bo   = (const float*)d_in[9];
    float* out = (float*)d_out;

    cudaFuncSetAttribute(attn_kernel, cudaFuncAttributeMaxDynamicSharedMemorySize, ATTN_SMEM_BYTES);

    bf16 *xh, *xl, *wvh, *wvl, *woh, *wol;
    cudaGetSymbolAddress((void**)&xh,  g_xh);  cudaGetSymbolAddress((void**)&xl,  g_xl);
    cudaGetSymbolAddress((void**)&wvh, g_Wvh); cudaGetSymbolAddress((void**)&wvl, g_Wvl);
    cudaGetSymbolAddress((void**)&woh, g_Woh); cudaGetSymbolAddress((void**)&wol, g_Wol);

    memfill_kernel<<<(BATCH * H * NM * DH + 255) / 256, 256>>>(mk, mv);
    split2v<<<(MROWS * DIM / 4 + 255) / 256, 256>>>(x,  xh,  xl,  MROWS * DIM / 4);
    split2v<<<(DIM * DIM / 4 + 255) / 256, 256>>>(Wv, wvh, wvl, DIM * DIM / 4);
    split2v<<<(DIM * DIM / 4 + 255) / 256, 256>>>(Wo, woh, wol, DIM * DIM / 4);

    gemm_qkv_kernel<<<dim3(DIM / 128, MROWS / 128, 2), 256>>>(x, Wq, Wk, Wv);  // Q,K fp32
    v_wmma<<<dim3(DIM / 64, MROWS / 128), 256>>>();                            // V bf16x3
    dots_kernel<<<dim3((JTOT + 127) / 128, NSEQ / 128, BATCH * H), 256>>>();
    attn_kernel<<<dim3(NSEQ, BATCH), 1024, ATTN_SMEM_BYTES>>>(pre, post);
    out_wmma<<<dim3(DIM / 64, MROWS / 128), 256>>>(bo, out);                   // out bf16x3
}

// round 14
// speedup vs baseline: 1.0973x; 1.0222x over previous
#include <cuda_runtime.h>
#include <cuda_bf16.h>
#include <mma.h>
#include <float.h>
#include <math.h>

using namespace nvcuda;
typedef __nv_bfloat16 bf16;
typedef unsigned long long ull;

#define BATCH 2
#define NSEQ  2048
#define DIM   1024
#define H     16
#define DH    64
#define NM    16
#define JTOT  2064          // NM + NSEQ
#define MROWS (BATCH*NSEQ)  // 4096

// ---- packed fp32x2 helpers (sm_103a): each lane is an independent IEEE fp32 op ----
__device__ __forceinline__ ull pk2(float lo, float hi) {
    ull r; asm("mov.b64 %0, {%1, %2};" : "=l"(r) : "f"(lo), "f"(hi)); return r;
}
__device__ __forceinline__ void fma2(ull& d, ull a, ull b) {
    asm("fma.rn.f32x2 %0, %1, %2, %0;" : "+l"(d) : "l"(a), "l"(b));
}
__device__ __forceinline__ float2 upk2(ull v) {
    float2 f; asm("mov.b64 {%0, %1}, %2;" : "=f"(f.x), "=f"(f.y) : "l"(v)); return f;
}

// ---------------- global scratch ----------------
__device__ float g_Q[BATCH][H][NSEQ][DH];
__device__ float g_K[BATCH][H][JTOT][DH];
__device__ float g_V[BATCH][H][JTOT][DH];
__device__ float g_dots[BATCH][H][NSEQ][JTOT];
__device__ bf16  g_xh[MROWS*DIM],  g_xl[MROWS*DIM];
__device__ bf16  g_Wvh[DIM*DIM],   g_Wvl[DIM*DIM];
__device__ bf16  g_Woh[DIM*DIM],   g_Wol[DIM*DIM];
__device__ bf16  g_ctxh[MROWS*DIM], g_ctxl[MROWS*DIM];

__device__ __forceinline__ void bsplit2(float v, bf16& h, bf16& l) {
    h = __float2bfloat16(v);
    l = __float2bfloat16(v - __bfloat162float(h));
}

// ---------------- fill mem_k / mem_v into K/V prefix ----------------
__global__ void memfill_kernel(const float* __restrict__ mk, const float* __restrict__ mv) {
    int idx = blockIdx.x * 256 + threadIdx.x;
    if (idx >= BATCH * H * NM * DH) return;
    int d = idx & 63;
    int j = (idx >> 6) & 15;
    int h = (idx >> 10) & 15;
    int b = idx >> 14;
    g_K[b][h][j][d] = mk[(h * NM + j) * DH + d];
    g_V[b][h][j][d] = mv[(h * NM + j) * DH + d];
}

// ---------------- bf16 hi/lo split, 4 elems per thread ----------------
__global__ void split2v(const float* __restrict__ s, bf16* __restrict__ h,
                        bf16* __restrict__ l, int n4) {
    int i = blockIdx.x * 256 + threadIdx.x;
    if (i >= n4) return;
    float4 v = *(const float4*)&s[i << 2];
    bf16 h0, l0, h1, l1, h2, l2, h3, l3;
    bsplit2(v.x, h0, l0); bsplit2(v.y, h1, l1);
    bsplit2(v.z, h2, l2); bsplit2(v.w, h3, l3);
    __nv_bfloat162 hp0; hp0.x = h0; hp0.y = h1;
    __nv_bfloat162 hp1; hp1.x = h2; hp1.y = h3;
    __nv_bfloat162 lp0; lp0.x = l0; lp0.y = l1;
    __nv_bfloat162 lp1; lp1.x = l2; lp1.y = l3;
    uint2 hu, lu;
    hu.x = *(unsigned*)&hp0; hu.y = *(unsigned*)&hp1;
    lu.x = *(unsigned*)&lp0; lu.y = *(unsigned*)&lp1;
    *(uint2*)&h[i << 2] = hu;
    *(uint2*)&l[i << 2] = lu;
}

// ============ 128x128x16 fp32 GEMM (Q,K) — f32x2 packed FMA, bit-identical ============
__global__ __launch_bounds__(256, 2) void gemm_qkv_kernel(
    const float* __restrict__ x, const float* __restrict__ Wq,
    const float* __restrict__ Wk, const float* __restrict__ Wv) {
    const int z = blockIdx.z;
    const float* W = (z == 0) ? Wq : (z == 1) ? Wk : Wv;
    __shared__ float As[2][16][132];
    __shared__ float Bs[2][16][132];
    const int m0 = blockIdx.y << 7;
    const int n0 = blockIdx.x << 7;
    const int tid = threadIdx.x;
    const int ty = tid >> 4, tx = tid & 15;
    const int arow = tid >> 2, acol = (tid & 3) << 2;
    const int brow = tid >> 5, bcol = (tid & 31) << 2;
    ull acc2[8][4];
#pragma unroll
    for (int i = 0; i < 8; i++)
#pragma unroll
        for (int j = 0; j < 4; j++) acc2[i][j] = 0ull;

    {
        float4 a0 = *(const float4*)&x[(m0 + arow) * DIM + acol];
        float4 a1 = *(const float4*)&x[(m0 + arow + 64) * DIM + acol];
        float4 b0 = *(const float4*)&W[brow * DIM + n0 + bcol];
        float4 b1 = *(const float4*)&W[(brow + 8) * DIM + n0 + bcol];
        As[0][acol + 0][arow] = a0.x; As[0][acol + 1][arow] = a0.y;
        As[0][acol + 2][arow] = a0.z; As[0][acol + 3][arow] = a0.w;
        As[0][acol + 0][arow + 64] = a1.x; As[0][acol + 1][arow + 64] = a1.y;
        As[0][acol + 2][arow + 64] = a1.z; As[0][acol + 3][arow + 64] = a1.w;
        *(float4*)&Bs[0][brow][bcol] = b0;
        *(float4*)&Bs[0][brow + 8][bcol] = b1;
    }
    __syncthreads();

    int cur = 0;
    for (int k0 = 0; k0 < DIM; k0 += 16) {
        const int nxt = k0 + 16;
        float4 na0, na1, nb0, nb1;
        if (nxt < DIM) {
            na0 = *(const float4*)&x[(m0 + arow) * DIM + nxt + acol];
            na1 = *(const float4*)&x[(m0 + arow + 64) * DIM + nxt + acol];
            nb0 = *(const float4*)&W[(nxt + brow) * DIM + n0 + bcol];
            nb1 = *(const float4*)&W[(nxt + brow + 8) * DIM + n0 + bcol];
        }
#pragma unroll
        for (int kk = 0; kk < 16; kk++) {
            float4 a04 = *(const float4*)&As[cur][kk][ty << 3];
            float4 a14 = *(const float4*)&As[cur][kk][(ty << 3) + 4];
            float4 b04 = *(const float4*)&Bs[cur][kk][tx << 3];
            float4 b14 = *(const float4*)&Bs[cur][kk][(tx << 3) + 4];
            ull b2[4] = {pk2(b04.x, b04.y), pk2(b04.z, b04.w),
                         pk2(b14.x, b14.y), pk2(b14.z, b14.w)};
            float av[8] = {a04.x, a04.y, a04.z, a04.w, a14.x, a14.y, a14.z, a14.w};
#pragma unroll
            for (int i = 0; i < 8; i++) {
                ull ad = pk2(av[i], av[i]);
#pragma unroll
                for (int j = 0; j < 4; j++) fma2(acc2[i][j], ad, b2[j]);
            }
        }
        if (nxt < DIM) {
            const int nb = cur ^ 1;
            As[nb][acol + 0][arow] = na0.x; As[nb][acol + 1][arow] = na0.y;
            As[nb][acol + 2][arow] = na0.z; As[nb][acol + 3][arow] = na0.w;
            As[nb][acol + 0][arow + 64] = na1.x; As[nb][acol + 1][arow + 64] = na1.y;
            As[nb][acol + 2][arow + 64] = na1.z; As[nb][acol + 3][arow + 64] = na1.w;
            *(float4*)&Bs[nb][brow][bcol] = nb0;
            *(float4*)&Bs[nb][brow + 8][bcol] = nb1;
            __syncthreads();
            cur = nb;
        }
    }
#pragma unroll
    for (int i = 0; i < 8; i++) {
        int m = m0 + (ty << 3) + i;
        int b = m >> 11;
        int irow = m & 2047;
#pragma unroll
        for (int j2 = 0; j2 < 2; j2++) {
            int c = n0 + (tx << 3) + j2 * 4;
            int h = c >> 6;
            int d = c & 63;
            float2 p0 = upk2(acc2[i][j2 * 2]);
            float2 p1 = upk2(acc2[i][j2 * 2 + 1]);
            float4 v = make_float4(p0.x, p0.y, p1.x, p1.y);
            if (z == 0)      *(float4*)&g_Q[b][h][irow][d] = v;
            else if (z == 1) *(float4*)&g_K[b][h][NM + irow][d] = v;
            else             *(float4*)&g_V[b][h][NM + irow][d] = v;
        }
    }
}

// ============ V projection: bf16x3 wmma (linear path) ============
__global__ __launch_bounds__(256) void v_wmma() {
    __shared__ bf16 sAh[128 * 40], sAl[128 * 40];
    __shared__ bf16 sBh[32 * 72],  sBl[32 * 72];
    const int m0 = blockIdx.y << 7;
    const int n0 = blockIdx.x << 6;
    const int tid = threadIdx.x;
    const int w = tid >> 5;
    const int wm = w >> 1, wn = w & 1;

    wmma::fragment<wmma::accumulator, 16, 16, 16, float> acc[2][2];
#pragma unroll
    for (int i = 0; i < 2; i++)
#pragma unroll
        for (int j = 0; j < 2; j++) wmma::fill_fragment(acc[i][j], 0.f);

    for (int k0 = 0; k0 < DIM; k0 += 32) {
        __syncthreads();
#pragma unroll
        for (int it = 0; it < 4; it++) {
            int idx = tid + it * 256;
            int r = idx >> 3, c = (idx & 7) << 2;
            long g = (long)(m0 + r) * DIM + k0 + c;
            *(uint2*)&sAh[r * 40 + c] = *(const uint2*)&g_xh[g];
            *(uint2*)&sAl[r * 40 + c] = *(const uint2*)&g_xl[g];
        }
#pragma unroll
        for (int it = 0; it < 2; it++) {
            int idx = tid + it * 256;
            int r = idx >> 4, c = (idx & 15) << 2;
            long g = (long)(k0 + r) * DIM + n0 + c;
            *(uint2*)&sBh[r * 72 + c] = *(const uint2*)&g_Wvh[g];
            *(uint2*)&sBl[r * 72 + c] = *(const uint2*)&g_Wvl[g];
        }
        __syncthreads();
#pragma unroll
        for (int ks = 0; ks < 2; ks++) {
            int k = ks << 4;
            wmma::fragment<wmma::matrix_a, 16, 16, 16, bf16, wmma::row_major> ah[2], al[2];
            wmma::fragment<wmma::matrix_b, 16, 16, 16, bf16, wmma::row_major> bh[2], bl[2];
#pragma unroll
            for (int fm = 0; fm < 2; fm++) {
                wmma::load_matrix_sync(ah[fm], &sAh[(wm * 32 + fm * 16) * 40 + k], 40);
                wmma::load_matrix_sync(al[fm], &sAl[(wm * 32 + fm * 16) * 40 + k], 40);
            }
#pragma unroll
            for (int fn = 0; fn < 2; fn++) {
                wmma::load_matrix_sync(bh[fn], &sBh[k * 72 + wn * 32 + fn * 16], 72);
                wmma::load_matrix_sync(bl[fn], &sBl[k * 72 + wn * 32 + fn * 16], 72);
            }
#pragma unroll
            for (int fm = 0; fm < 2; fm++)
#pragma unroll
                for (int fn = 0; fn < 2; fn++) {
                    wmma::mma_sync(acc[fm][fn], ah[fm], bl[fn], acc[fm][fn]);
                    wmma::mma_sync(acc[fm][fn], al[fm], bh[fn], acc[fm][fn]);
                    wmma::mma_sync(acc[fm][fn], ah[fm], bh[fn], acc[fm][fn]);
                }
        }
    }
    const int h = n0 >> 6;
#pragma unroll
    for (int fm = 0; fm < 2; fm++) {
        int m = m0 + wm * 32 + fm * 16;
        int b = m >> 11;
        int irow = m & 2047;
#pragma unroll
        for (int fn = 0; fn < 2; fn++) {
            int d = wn * 32 + fn * 16;
            wmma::store_matrix_sync(&g_V[b][h][NM + irow][d], acc[fm][fn], DH, wmma::mem_row_major);
        }
    }
}

// ============ dots: 128x128x64 tiles, f32x2 packed FMA, causal skip ============
__global__ __launch_bounds__(256, 2) void dots_kernel() {
    const int bh = blockIdx.z;
    const int b = bh >> 4, h = bh & 15;
    const int i0 = blockIdx.y << 7;
    const int j0 = blockIdx.x << 7;
    if (j0 > i0 + 127 + NM) return;
    __shared__ float Qs[64][132];
    __shared__ float Ks[64][132];
    const int tid = threadIdx.x;
    const int ty = tid >> 4, tx = tid & 15;
    const int lr = tid >> 4;
    const int lc = (tid & 15) << 2;
#pragma unroll
    for (int rr = 0; rr < 128; rr += 16) {
        int r = lr + rr;
        float4 q = *(const float4*)&g_Q[b][h][i0 + r][lc];
        Qs[lc + 0][r] = q.x; Qs[lc + 1][r] = q.y;
        Qs[lc + 2][r] = q.z; Qs[lc + 3][r] = q.w;
        int j = j0 + r;
        float4 kv = make_float4(0.f, 0.f, 0.f, 0.f);
        if (j < JTOT) kv = *(const float4*)&g_K[b][h][j][lc];
        Ks[lc + 0][r] = kv.x; Ks[lc + 1][r] = kv.y;
        Ks[lc + 2][r] = kv.z; Ks[lc + 3][r] = kv.w;
    }
    __syncthreads();
    ull acc2[8][4];
#pragma unroll
    for (int i = 0; i < 8; i++)
#pragma unroll
        for (int j = 0; j < 4; j++) acc2[i][j] = 0ull;
#pragma unroll
    for (int kk = 0; kk < 64; kk++) {
        float4 a04 = *(const float4*)&Qs[kk][ty << 3];
        float4 a14 = *(const float4*)&Qs[kk][(ty << 3) + 4];
        float4 b04 = *(const float4*)&Ks[kk][tx << 3];
        float4 b14 = *(const float4*)&Ks[kk][(tx << 3) + 4];
        ull b2[4] = {pk2(b04.x, b04.y), pk2(b04.z, b04.w),
                     pk2(b14.x, b14.y), pk2(b14.z, b14.w)};
        float av[8] = {a04.x, a04.y, a04.z, a04.w, a14.x, a14.y, a14.z, a14.w};
#pragma unroll
        for (int i = 0; i < 8; i++) {
            ull ad = pk2(av[i], av[i]);
#pragma unroll
            for (int j = 0; j < 4; j++) fma2(acc2[i][j], ad, b2[j]);
        }
    }
    const float scale = 0.125f;
#pragma unroll
    for (int i = 0; i < 8; i++) {
        int irow = i0 + (ty << 3) + i;
#pragma unroll
        for (int j2 = 0; j2 < 2; j2++) {
            int jcol = j0 + (tx << 3) + j2 * 4;
            if (jcol < JTOT) {
                float2 p0 = upk2(acc2[i][j2 * 2]);
                float2 p1 = upk2(acc2[i][j2 * 2 + 1]);
                float4 v = make_float4(p0.x * scale, p0.y * scale,
                                       p1.x * scale, p1.y * scale);
                *(float4*)&g_dots[b][h][irow][jcol] = v;
            }
        }
    }
}

// ============ fused per-row attention: 1024 threads, f32x2 premix ============
#define ATTN_SMEM_FLOATS (H*JTOT + 256 + 256 + H*64*8 + 32 + 16 + 512)
#define ATTN_SMEM_INTS   (JTOT + JTOT)
#define ATTN_SMEM_BYTES  ((ATTN_SMEM_FLOATS + ATTN_SMEM_INTS) * 4)

#define INS8(vv) do { float _v = (vv); \
    if (_v > t8[7]) { t8[7] = _v; \
        _Pragma("unroll") \
        for (int _q = 7; _q >= 1; _q--) \
            if (t8[_q] > t8[_q-1]) { float _t = t8[_q]; t8[_q] = t8[_q-1]; t8[_q-1] = _t; } \
    } } while (0)

__global__ __launch_bounds__(1024) void attn_kernel(
    const float* __restrict__ pre, const float* __restrict__ post) {
    const int i = (NSEQ - 1) - blockIdx.x;
    const int b = blockIdx.y;
    const int tid = threadIdx.x;
    extern __shared__ float sm[];
    float* s_d    = sm;                       // [16][2064]
    float* s_pre  = s_d + H * JTOT;           // [256]
    float* s_post = s_pre + 256;              // [256]
    float* s_top  = s_post + 256;             // [16][64][8]
    float* s_zred = s_top + H * 64 * 8;       // [32]
    float* s_inv  = s_zred + 32;              // [16]
    ull*   s_pre2 = (ull*)(s_inv + 16);       // [256] packed (w,w) — 8B aligned
    int* s_flag = (int*)(s_pre2 + 256);       // [2064]
    int* s_list = s_flag + JTOT;              // [2064]
    __shared__ int s_wsum[32];

    if (tid < 256) {
        float w = pre[tid];
        s_pre[tid]  = w;
        s_pre2[tid] = pk2(w, w);
        s_post[tid] = post[tid];
    }
    const int nv = i + NM + 1;
    __syncthreads();

    // ---- fused load + premix + flag zero (f32x2 chains; bit-identical per lane) ----
    {
        const float* dbase = &g_dots[b][0][i][0];
        const long hstride = (long)NSEQ * JTOT;
        const int npair = (nv + 1) >> 1;
        for (int p = tid; p < npair; p += 1024) {
            int j = p << 1;
            s_flag[j] = 0;
            if (j + 1 < nv) {
                s_flag[j + 1] = 0;
                ull r2[16];
#pragma unroll
                for (int h2 = 0; h2 < 16; h2++)
                    r2[h2] = *(const ull*)&dbase[h2 * hstride + j];
#pragma unroll
                for (int k = 0; k < 16; k++) {
                    ull a2 = 0ull;
#pragma unroll
                    for (int h2 = 0; h2 < 16; h2++)
                        fma2(a2, r2[h2], s_pre2[h2 * 16 + k]);
                    *(ull*)&s_d[k * JTOT + j] = a2;
                }
            } else {
                float r1[16];
#pragma unroll
                for (int h2 = 0; h2 < 16; h2++) r1[h2] = dbase[h2 * hstride + j];
#pragma unroll
                for (int k = 0; k < 16; k++) {
                    float a = 0.f;
#pragma unroll
                    for (int h2 = 0; h2 < 16; h2++) a += r1[h2] * s_pre[h2 * 16 + k];
                    s_d[k * JTOT + j] = a;
                }
            }
        }
    }
    __syncthreads();

    // ---- top-8 per row: 64 threads per row, float4 scan ----
    const int row = tid >> 6;
    const int t64 = tid & 63;
    const float* rd = s_d + row * JTOT;
    float t8[8];
#pragma unroll
    for (int q = 0; q < 8; q++) t8[q] = -FLT_MAX;
    {
        const int n4 = nv >> 2;
        for (int q = t64; q < n4; q += 64) {
            float4 v4 = *(const float4*)&rd[q << 2];
            INS8(v4.x); INS8(v4.y); INS8(v4.z); INS8(v4.w);
        }
        int tail = nv & 3;
        if (t64 < tail) INS8(rd[(n4 << 2) + t64]);
    }
    {
        float* myl = s_top + (row * 64 + t64) * 8;
#pragma unroll
        for (int q = 0; q < 8; q++) myl[q] = t8[q];
    }
    __syncthreads();
    if (t64 < 32) {
        float* A  = s_top + (row * 64 + t64) * 8;
        float* B2 = s_top + (row * 64 + t64 + 32) * 8;
        float out[8];
        int ia = 0, ib = 0;
#pragma unroll
        for (int r2 = 0; r2 < 8; r2++) {
            float va = A[ia];
            float vb = B2[ib];
            bool ta = (va >= vb);
            out[r2] = ta ? va : vb;
            ia += ta ? 1 : 0;
            ib += ta ? 0 : 1;
        }
#pragma unroll
        for (int r2 = 0; r2 < 8; r2++) A[r2] = out[r2];
    }
    __syncthreads();
    if (t64 < 32) {
#pragma unroll
        for (int L = 16; L >= 1; L >>= 1) {
            if (t64 < L) {
                float* A  = s_top + (row * 64 + t64) * 8;
                float* B2 = s_top + (row * 64 + t64 + L) * 8;
                float out[8];
                int ia = 0, ib = 0;
#pragma unroll
                for (int r2 = 0; r2 < 8; r2++) {
                    float va = A[ia];
                    float vb = B2[ib];
                    bool ta = (va >= vb);
                    out[r2] = ta ? va : vb;
                    ia += ta ? 1 : 0;
                    ib += ta ? 0 : 1;
                }
#pragma unroll
                for (int r2 = 0; r2 < 8; r2++) A[r2] = out[r2];
            }
            __syncwarp();
        }
    }
    __syncthreads();
    const float thr = s_top[row * 512 + 7];
    const float mx  = s_top[row * 512 + 0];

    // ---- exp-sum pass ----
    float psum = 0.f;
    {
        float* wrow = s_d + row * JTOT;
        const int np2 = nv >> 1;
        for (int q = t64; q < np2; q += 64) {
            int j = q << 1;
            float2 v = *(const float2*)&wrow[j];
            bool k0 = (v.x >= thr), k1 = (v.y >= thr);
            float e0 = k0 ? __expf(v.x - mx) : 0.f;
            float e1 = k1 ? __expf(v.y - mx) : 0.f;
            psum += e0; psum += e1;
            *(float2*)&wrow[j] = make_float2(e0, e1);
            if (k0) s_flag[j] = 1;
            if (k1) s_flag[j + 1] = 1;
        }
        if ((nv & 1) && t64 == 0) {
            int j = nv - 1;
            float v = wrow[j];
            if (v >= thr) { float e = __expf(v - mx); psum += e; wrow[j] = e; s_flag[j] = 1; }
            else wrow[j] = 0.f;
        }
    }
#pragma unroll
    for (int off = 16; off >= 1; off >>= 1)
        psum += __shfl_down_sync(0xffffffffu, psum, off);
    if ((tid & 31) == 0) s_zred[tid >> 5] = psum;
    __syncthreads();
    if (t64 == 0) s_inv[row] = 1.f / (s_zred[row * 2] + s_zred[row * 2 + 1]);

    // ---- survivor compaction ----
    const int lane = tid & 31;
    const int wid  = tid >> 5;
    const int CH = 3;
    int base = tid * CH;
    int end = base + CH; if (end > nv) end = nv;
    int c = 0;
    for (int j = base; j < end; j++) c += s_flag[j];
    int val = c;
#pragma unroll
    for (int off = 1; off < 32; off <<= 1) {
        int u = __shfl_up_sync(0xffffffffu, val, off);
        if (lane >= off) val += u;
    }
    if (lane == 31) s_wsum[wid] = val;
    __syncthreads();
    if (tid < 32) {
        int v = s_wsum[tid];
#pragma unroll
        for (int off = 1; off < 32; off <<= 1) {
            int u = __shfl_up_sync(0xffffffffu, v, off);
            if (tid >= off) v += u;
        }
        s_wsum[tid] = v;
    }
    __syncthreads();
    {
        int pos = (wid > 0 ? s_wsum[wid - 1] : 0) + (val - c);
        for (int j = base; j < end; j++)
            if (s_flag[j]) s_list[pos++] = j;
    }
    const int cnt = s_wsum[31];
    __syncthreads();

    // ---- post-mix at survivor columns (inv folded in) ----
    for (int sI = tid; sI < cnt; sI += 1024) {
        int j = s_list[sI];
        float a[16];
#pragma unroll
        for (int h2 = 0; h2 < 16; h2++) a[h2] = s_d[h2 * JTOT + j] * s_inv[h2];
#pragma unroll
        for (int k = 0; k < 16; k++) {
            float acc2 = 0.f;
#pragma unroll
            for (int h2 = 0; h2 < 16; h2++) acc2 += a[h2] * s_post[h2 * 16 + k];
            s_d[k * JTOT + j] = acc2;
        }
    }
    __syncthreads();

    // ---- sparse attn2 @ V: 64 threads per head, unrolled x4 for MLP ----
    const int kk2 = tid >> 6;   // head
    const int d = tid & 63;     // dim
    float acc = 0.f;
    const float* Vb = &g_V[b][kk2][0][0];
    const float* wr = s_d + kk2 * JTOT;
    int s2 = 0;
    for (; s2 + 3 < cnt; s2 += 4) {
        int4 j4 = *(const int4*)&s_list[s2];
        float w0 = wr[j4.x], w1 = wr[j4.y], w2 = wr[j4.z], w3 = wr[j4.w];
        float v0 = Vb[j4.x * 64 + d];
        float v1 = Vb[j4.y * 64 + d];
        float v2 = Vb[j4.z * 64 + d];
        float v3 = Vb[j4.w * 64 + d];
        acc += w0 * v0 + w1 * v1;
        acc += w2 * v2 + w3 * v3;
    }
    for (; s2 < cnt; s2++) {
        int ja = s_list[s2];
        acc += wr[ja] * Vb[ja * 64 + d];
    }
    bf16 hx, lx;
    bsplit2(acc, hx, lx);
    long off2 = (long)(b * NSEQ + i) * DIM + kk2 * 64 + d;
    g_ctxh[off2] = hx;
    g_ctxl[off2] = lx;
}

// ============ output projection: bf16x3 wmma + bias (linear path) ============
__global__ __launch_bounds__(256) void out_wmma(const float* __restrict__ bo,
                                                float* __restrict__ outp) {
    __shared__ float sEpi[128 * 72];
    bf16* sAh = (bf16*)sEpi;
    bf16* sAl = sAh + 128 * 40;
    bf16* sBh = sAl + 128 * 40;
    bf16* sBl = sBh + 32 * 72;
    const int m0 = blockIdx.y << 7;
    const int n0 = blockIdx.x << 6;
    const int tid = threadIdx.x;
    const int w = tid >> 5;
    const int wm = w >> 1, wn = w & 1;

    wmma::fragment<wmma::accumulator, 16, 16, 16, float> acc[2][2];
#pragma unroll
    for (int i = 0; i < 2; i++)
#pragma unroll
        for (int j = 0; j < 2; j++) wmma::fill_fragment(acc[i][j], 0.f);

    for (int k0 = 0; k0 < DIM; k0 += 32) {
        __syncthreads();
#pragma unroll
        for (int it = 0; it < 4; it++) {
            int idx = tid + it * 256;
            int r = idx >> 3, c = (idx & 7) << 2;
            long g = (long)(m0 + r) * DIM + k0 + c;
            *(uint2*)&sAh[r * 40 + c] = *(const uint2*)&g_ctxh[g];
            *(uint2*)&sAl[r * 40 + c] = *(const uint2*)&g_ctxl[g];
        }
#pragma unroll
        for (int it = 0; it < 2; it++) {
            int idx = tid + it * 256;
            int r = idx >> 4, c = (idx & 15) << 2;
            long g = (long)(k0 + r) * DIM + n0 + c;
            *(uint2*)&sBh[r * 72 + c] = *(const uint2*)&g_Woh[g];
            *(uint2*)&sBl[r * 72 + c] = *(const uint2*)&g_Wol[g];
        }
        __syncthreads();
#pragma unroll
        for (int ks = 0; ks < 2; ks++) {
            int k = ks << 4;
            wmma::fragment<wmma::matrix_a, 16, 16, 16, bf16, wmma::row_major> ah[2], al[2];
            wmma::fragment<wmma::matrix_b, 16, 16, 16, bf16, wmma::row_major> bh[2], bl[2];
#pragma unroll
            for (int fm = 0; fm < 2; fm++) {
                wmma::load_matrix_sync(ah[fm], &sAh[(wm * 32 + fm * 16) * 40 + k], 40);
                wmma::load_matrix_sync(al[fm], &sAl[(wm * 32 + fm * 16) * 40 + k], 40);
            }
#pragma unroll
            for (int fn = 0; fn < 2; fn++) {
                wmma::load_matrix_sync(bh[fn], &sBh[k * 72 + wn * 32 + fn * 16], 72);
                wmma::load_matrix_sync(bl[fn], &sBl[k * 72 + wn * 32 + fn * 16], 72);
            }
#pragma unroll
            for (int fm = 0; fm < 2; fm++)
#pragma unroll
                for (int fn = 0; fn < 2; fn++) {
                    wmma::mma_sync(acc[fm][fn], ah[fm], bl[fn], acc[fm][fn]);
                    wmma::mma_sync(acc[fm][fn], al[fm], bh[fn], acc[fm][fn]);
                    wmma::mma_sync(acc[fm][fn], ah[fm], bh[fn], acc[fm][fn]);
                }
        }
    }
    __syncthreads();
#pragma unroll
    for (int fm = 0; fm < 2; fm++)
#pragma unroll
        for (int fn = 0; fn < 2; fn++)
            wmma::store_matrix_sync(&sEpi[(wm * 32 + fm * 16) * 72 + wn * 32 + fn * 16],
                                    acc[fm][fn], 72, wmma::mem_row_major);
    __syncthreads();
#pragma unroll
    for (int it = 0; it < 8; it++) {
        int idx = tid + it * 256;
        int r = idx >> 4, c = (idx & 15) << 2;
        float4 v = *(const float4*)&sEpi[r * 72 + c];
        float4 bias = *(const float4*)&bo[n0 + c];
        v.x += bias.x; v.y += bias.y; v.z += bias.z; v.w += bias.w;
        *(float4*)&outp[(m0 + r) * DIM + n0 + c] = v;
    }
}

// ---------------- launch ----------------
extern "C" void kernel_launch(void* const* d_in, const int* in_sizes, int n_in,
                              void* d_out, int out_size) {
    const float* x    = (const float*)d_in[0];
    const float* Wq   = (const float*)d_in[1];
    const float* Wk   = (const float*)d_in[2];
    const float* Wv   = (const float*)d_in[3];
    const float* pre  = (const float*)d_in[4];
    const float* post = (const float*)d_in[5];
    const float* mk   = (const float*)d_in[6];
    const float* mv   = (const float*)d_in[7];
    const float* Wo   = (const float*)d_in[8];
    const float* bo   = (const float*)d_in[9];
    float* out = (float*)d_out;

    cudaFuncSetAttribute(attn_kernel, cudaFuncAttributeMaxDynamicSharedMemorySize, ATTN_SMEM_BYTES);

    bf16 *xh, *xl, *wvh, *wvl, *woh, *wol;
    cudaGetSymbolAddress((void**)&xh,  g_xh);  cudaGetSymbolAddress((void**)&xl,  g_xl);
    cudaGetSymbolAddress((void**)&wvh, g_Wvh); cudaGetSymbolAddress((void**)&wvl, g_Wvl);
    cudaGetSymbolAddress((void**)&woh, g_Woh); cudaGetSymbolAddress((void**)&wol, g_Wol);

    memfill_kernel<<<(BATCH * H * NM * DH + 255) / 256, 256>>>(mk, mv);
    split2v<<<(MROWS * DIM / 4 + 255) / 256, 256>>>(x,  xh,  xl,  MROWS * DIM / 4);
    split2v<<<(DIM * DIM / 4 + 255) / 256, 256>>>(Wv, wvh, wvl, DIM * DIM / 4);
    split2v<<<(DIM * DIM / 4 + 255) / 256, 256>>>(Wo, woh, wol, DIM * DIM / 4);

    gemm_qkv_kernel<<<dim3(DIM / 128, MROWS / 128, 2), 256>>>(x, Wq, Wk, Wv);  // Q,K fp32 (f32x2)
    v_wmma<<<dim3(DIM / 64, MROWS / 128), 256>>>();                            // V bf16x3
    dots_kernel<<<dim3((JTOT + 127) / 128, NSEQ / 128, BATCH * H), 256>>>();   // dots f32x2
    attn_kernel<<<dim3(NSEQ, BATCH), 1024, ATTN_SMEM_BYTES>>>(pre, post);
    out_wmma<<<dim3(DIM / 64, MROWS / 128), 256>>>(bo, out);                   // out bf16x3
}

// round 15
// speedup vs baseline: 1.1129x; 1.0142x over previous
#include <cuda_runtime.h>
#include <cuda_bf16.h>
#include <mma.h>
#include <float.h>
#include <math.h>

using namespace nvcuda;
typedef __nv_bfloat16 bf16;
typedef unsigned long long ull;

#define BATCH 2
#define NSEQ  2048
#define DIM   1024
#define H     16
#define DH    64
#define NM    16
#define JTOT  2064          // NM + NSEQ
#define MROWS (BATCH*NSEQ)  // 4096

// ---- packed fp32x2 helpers ----
__device__ __forceinline__ ull pk2(float lo, float hi) {
    ull r; asm("mov.b64 %0, {%1, %2};" : "=l"(r) : "f"(lo), "f"(hi)); return r;
}
__device__ __forceinline__ void fma2(ull& d, ull a, ull b) {
    asm("fma.rn.f32x2 %0, %1, %2, %0;" : "+l"(d) : "l"(a), "l"(b));
}
__device__ __forceinline__ float2 upk2(ull v) {
    float2 f; asm("mov.b64 {%0, %1}, %2;" : "=f"(f.x), "=f"(f.y) : "l"(v)); return f;
}

// ---------------- global scratch ----------------
__device__ float g_Q[BATCH][H][NSEQ][DH];
__device__ float g_K[BATCH][H][JTOT][DH];
__device__ float g_V[BATCH][H][JTOT][DH];
__device__ float g_dots[BATCH][H][NSEQ][JTOT];
__device__ bf16  g_xh[MROWS*DIM],  g_xl[MROWS*DIM];
__device__ bf16  g_Wvh[DIM*DIM],   g_Wvl[DIM*DIM];
__device__ bf16  g_Woh[DIM*DIM],   g_Wol[DIM*DIM];
__device__ bf16  g_ctxh[MROWS*DIM], g_ctxl[MROWS*DIM];

__device__ __forceinline__ void bsplit2(float v, bf16& h, bf16& l) {
    h = __float2bfloat16(v);
    l = __float2bfloat16(v - __bfloat162float(h));
}

// ---------------- fill mem_k / mem_v into K/V prefix ----------------
__global__ void memfill_kernel(const float* __restrict__ mk, const float* __restrict__ mv) {
    int idx = blockIdx.x * 256 + threadIdx.x;
    if (idx >= BATCH * H * NM * DH) return;
    int d = idx & 63;
    int j = (idx >> 6) & 15;
    int h = (idx >> 10) & 15;
    int b = idx >> 14;
    g_K[b][h][j][d] = mk[(h * NM + j) * DH + d];
    g_V[b][h][j][d] = mv[(h * NM + j) * DH + d];
}

// ---------------- all bf16 hi/lo splits in ONE launch ----------------
#define NX4 (MROWS*DIM/4)
#define NW4 (DIM*DIM/4)
__global__ void split_all(const float* __restrict__ x, const float* __restrict__ wv,
                          const float* __restrict__ wo) {
    int i = blockIdx.x * 256 + threadIdx.x;
    const float* s; bf16 *h, *l; int idx;
    if (i < NX4)            { s = x;  h = g_xh;  l = g_xl;  idx = i; }
    else if (i < NX4 + NW4) { s = wv; h = g_Wvh; l = g_Wvl; idx = i - NX4; }
    else if (i < NX4 + 2*NW4) { s = wo; h = g_Woh; l = g_Wol; idx = i - NX4 - NW4; }
    else return;
    float4 v = *(const float4*)&s[idx << 2];
    bf16 h0, l0, h1, l1, h2, l2, h3, l3;
    bsplit2(v.x, h0, l0); bsplit2(v.y, h1, l1);
    bsplit2(v.z, h2, l2); bsplit2(v.w, h3, l3);
    __nv_bfloat162 hp0; hp0.x = h0; hp0.y = h1;
    __nv_bfloat162 hp1; hp1.x = h2; hp1.y = h3;
    __nv_bfloat162 lp0; lp0.x = l0; lp0.y = l1;
    __nv_bfloat162 lp1; lp1.x = l2; lp1.y = l3;
    uint2 hu, lu;
    hu.x = *(unsigned*)&hp0; hu.y = *(unsigned*)&hp1;
    lu.x = *(unsigned*)&lp0; lu.y = *(unsigned*)&lp1;
    *(uint2*)&h[idx << 2] = hu;
    *(uint2*)&l[idx << 2] = lu;
}

// ============ QK fp32 block (128x128x16, f32x2 FMA — bit-identical to R14) ============
__device__ __forceinline__ void qk_block(char* smraw, const float* __restrict__ x,
                                         const float* __restrict__ W, int z,
                                         int bx, int by) {
    float* As = (float*)smraw;              // [2][16][132]
    float* Bs = As + 2 * 16 * 132;          // [2][16][132]
    const int m0 = by << 7;
    const int n0 = bx << 7;
    const int tid = threadIdx.x;
    const int ty = tid >> 4, tx = tid & 15;
    const int arow = tid >> 2, acol = (tid & 3) << 2;
    const int brow = tid >> 5, bcol = (tid & 31) << 2;
    ull acc2[8][4];
#pragma unroll
    for (int i = 0; i < 8; i++)
#pragma unroll
        for (int j = 0; j < 4; j++) acc2[i][j] = 0ull;

#define AS(bf, k, m) As[((bf) * 16 + (k)) * 132 + (m)]
#define BS(bf, k, n) Bs[((bf) * 16 + (k)) * 132 + (n)]
    {
        float4 a0 = *(const float4*)&x[(m0 + arow) * DIM + acol];
        float4 a1 = *(const float4*)&x[(m0 + arow + 64) * DIM + acol];
        float4 b0 = *(const float4*)&W[brow * DIM + n0 + bcol];
        float4 b1 = *(const float4*)&W[(brow + 8) * DIM + n0 + bcol];
        AS(0, acol + 0, arow) = a0.x; AS(0, acol + 1, arow) = a0.y;
        AS(0, acol + 2, arow) = a0.z; AS(0, acol + 3, arow) = a0.w;
        AS(0, acol + 0, arow + 64) = a1.x; AS(0, acol + 1, arow + 64) = a1.y;
        AS(0, acol + 2, arow + 64) = a1.z; AS(0, acol + 3, arow + 64) = a1.w;
        *(float4*)&BS(0, brow, bcol) = b0;
        *(float4*)&BS(0, brow + 8, bcol) = b1;
    }
    __syncthreads();

    int cur = 0;
    for (int k0 = 0; k0 < DIM; k0 += 16) {
        const int nxt = k0 + 16;
        float4 na0, na1, nb0, nb1;
        if (nxt < DIM) {
            na0 = *(const float4*)&x[(m0 + arow) * DIM + nxt + acol];
            na1 = *(const float4*)&x[(m0 + arow + 64) * DIM + nxt + acol];
            nb0 = *(const float4*)&W[(nxt + brow) * DIM + n0 + bcol];
            nb1 = *(const float4*)&W[(nxt + brow + 8) * DIM + n0 + bcol];
        }
#pragma unroll
        for (int kk = 0; kk < 16; kk++) {
            float4 a04 = *(const float4*)&AS(cur, kk, ty << 3);
            float4 a14 = *(const float4*)&AS(cur, kk, (ty << 3) + 4);
            float4 b04 = *(const float4*)&BS(cur, kk, tx << 3);
            float4 b14 = *(const float4*)&BS(cur, kk, (tx << 3) + 4);
            ull b2[4] = {pk2(b04.x, b04.y), pk2(b04.z, b04.w),
                         pk2(b14.x, b14.y), pk2(b14.z, b14.w)};
            float av[8] = {a04.x, a04.y, a04.z, a04.w, a14.x, a14.y, a14.z, a14.w};
#pragma unroll
            for (int i = 0; i < 8; i++) {
                ull ad = pk2(av[i], av[i]);
#pragma unroll
                for (int j = 0; j < 4; j++) fma2(acc2[i][j], ad, b2[j]);
            }
        }
        if (nxt < DIM) {
            const int nb = cur ^ 1;
            AS(nb, acol + 0, arow) = na0.x; AS(nb, acol + 1, arow) = na0.y;
            AS(nb, acol + 2, arow) = na0.z; AS(nb, acol + 3, arow) = na0.w;
            AS(nb, acol + 0, arow + 64) = na1.x; AS(nb, acol + 1, arow + 64) = na1.y;
            AS(nb, acol + 2, arow + 64) = na1.z; AS(nb, acol + 3, arow + 64) = na1.w;
            *(float4*)&BS(nb, brow, bcol) = nb0;
            *(float4*)&BS(nb, brow + 8, bcol) = nb1;
            __syncthreads();
            cur = nb;
        }
    }
#undef AS
#undef BS
#pragma unroll
    for (int i = 0; i < 8; i++) {
        int m = m0 + (ty << 3) + i;
        int b = m >> 11;
        int irow = m & 2047;
#pragma unroll
        for (int j2 = 0; j2 < 2; j2++) {
            int c = n0 + (tx << 3) + j2 * 4;
            int h = c >> 6;
            int d = c & 63;
            float2 p0 = upk2(acc2[i][j2 * 2]);
            float2 p1 = upk2(acc2[i][j2 * 2 + 1]);
            float4 v = make_float4(p0.x, p0.y, p1.x, p1.y);
            if (z == 0) *(float4*)&g_Q[b][h][irow][d] = v;
            else        *(float4*)&g_K[b][h][NM + irow][d] = v;
        }
    }
}

// ============ V bf16x3 wmma block (128x64x32 — bit-identical to R14 v_wmma) ============
__device__ __forceinline__ void v_block(char* smraw, int bx, int by) {
    bf16* sAh = (bf16*)smraw;           // 128*40
    bf16* sAl = sAh + 128 * 40;
    bf16* sBh = sAl + 128 * 40;         // 32*72
    bf16* sBl = sBh + 32 * 72;
    const int m0 = by << 7;
    const int n0 = bx << 6;
    const int tid = threadIdx.x;
    const int w = tid >> 5;
    const int wm = w >> 1, wn = w & 1;

    wmma::fragment<wmma::accumulator, 16, 16, 16, float> acc[2][2];
#pragma unroll
    for (int i = 0; i < 2; i++)
#pragma unroll
        for (int j = 0; j < 2; j++) wmma::fill_fragment(acc[i][j], 0.f);

    for (int k0 = 0; k0 < DIM; k0 += 32) {
        __syncthreads();
#pragma unroll
        for (int it = 0; it < 4; it++) {
            int idx = tid + it * 256;
            int r = idx >> 3, c = (idx & 7) << 2;
            long g = (long)(m0 + r) * DIM + k0 + c;
            *(uint2*)&sAh[r * 40 + c] = *(const uint2*)&g_xh[g];
            *(uint2*)&sAl[r * 40 + c] = *(const uint2*)&g_xl[g];
        }
#pragma unroll
        for (int it = 0; it < 2; it++) {
            int idx = tid + it * 256;
            int r = idx >> 4, c = (idx & 15) << 2;
            long g = (long)(k0 + r) * DIM + n0 + c;
            *(uint2*)&sBh[r * 72 + c] = *(const uint2*)&g_Wvh[g];
            *(uint2*)&sBl[r * 72 + c] = *(const uint2*)&g_Wvl[g];
        }
        __syncthreads();
#pragma unroll
        for (int ks = 0; ks < 2; ks++) {
            int k = ks << 4;
            wmma::fragment<wmma::matrix_a, 16, 16, 16, bf16, wmma::row_major> ah[2], al[2];
            wmma::fragment<wmma::matrix_b, 16, 16, 16, bf16, wmma::row_major> bh[2], bl[2];
#pragma unroll
            for (int fm = 0; fm < 2; fm++) {
                wmma::load_matrix_sync(ah[fm], &sAh[(wm * 32 + fm * 16) * 40 + k], 40);
                wmma::load_matrix_sync(al[fm], &sAl[(wm * 32 + fm * 16) * 40 + k], 40);
            }
#pragma unroll
            for (int fn = 0; fn < 2; fn++) {
                wmma::load_matrix_sync(bh[fn], &sBh[k * 72 + wn * 32 + fn * 16], 72);
                wmma::load_matrix_sync(bl[fn], &sBl[k * 72 + wn * 32 + fn * 16], 72);
            }
#pragma unroll
            for (int fm = 0; fm < 2; fm++)
#pragma unroll
                for (int fn = 0; fn < 2; fn++) {
                    wmma::mma_sync(acc[fm][fn], ah[fm], bl[fn], acc[fm][fn]);
                    wmma::mma_sync(acc[fm][fn], al[fm], bh[fn], acc[fm][fn]);
                    wmma::mma_sync(acc[fm][fn], ah[fm], bh[fn], acc[fm][fn]);
                }
        }
    }
    const int h = n0 >> 6;
#pragma unroll
    for (int fm = 0; fm < 2; fm++) {
        int m = m0 + wm * 32 + fm * 16;
        int b = m >> 11;
        int irow = m & 2047;
#pragma unroll
        for (int fn = 0; fn < 2; fn++) {
            int d = wn * 32 + fn * 16;
            wmma::store_matrix_sync(&g_V[b][h][NM + irow][d], acc[fm][fn], DH, wmma::mem_row_major);
        }
    }
}

// ============ fused QK (fp32 pipe) + V (tensor pipe): interleaved blocks ============
#define QKV_FUSED_SMEM (2 * 16 * 132 * 2 * 4)   // 33792 B (>= V path's 29696 B)
__global__ __launch_bounds__(256, 2) void qkv_fused(
    const float* __restrict__ x, const float* __restrict__ Wq,
    const float* __restrict__ Wk) {
    extern __shared__ char smraw[];
    const int bid = blockIdx.x;
    if ((bid & 1) == 0) {
        int qb = bid >> 1;          // [0,512)
        int z = qb >> 8;
        int rem = qb & 255;
        qk_block(smraw, x, (z == 0) ? Wq : Wk, z, rem & 7, rem >> 3);
    } else {
        int vb = bid >> 1;          // [0,512)
        v_block(smraw, vb & 15, vb >> 4);
    }
}

// ============ dots: 128x128x64 tiles, f32x2 packed FMA, causal skip ============
__global__ __launch_bounds__(256, 2) void dots_kernel() {
    const int bh = blockIdx.z;
    const int b = bh >> 4, h = bh & 15;
    const int i0 = blockIdx.y << 7;
    const int j0 = blockIdx.x << 7;
    if (j0 > i0 + 127 + NM) return;
    __shared__ float Qs[64][132];
    __shared__ float Ks[64][132];
    const int tid = threadIdx.x;
    const int ty = tid >> 4, tx = tid & 15;
    const int lr = tid >> 4;
    const int lc = (tid & 15) << 2;
#pragma unroll
    for (int rr = 0; rr < 128; rr += 16) {
        int r = lr + rr;
        float4 q = *(const float4*)&g_Q[b][h][i0 + r][lc];
        Qs[lc + 0][r] = q.x; Qs[lc + 1][r] = q.y;
        Qs[lc + 2][r] = q.z; Qs[lc + 3][r] = q.w;
        int j = j0 + r;
        float4 kv = make_float4(0.f, 0.f, 0.f, 0.f);
        if (j < JTOT) kv = *(const float4*)&g_K[b][h][j][lc];
        Ks[lc + 0][r] = kv.x; Ks[lc + 1][r] = kv.y;
        Ks[lc + 2][r] = kv.z; Ks[lc + 3][r] = kv.w;
    }
    __syncthreads();
    ull acc2[8][4];
#pragma unroll
    for (int i = 0; i < 8; i++)
#pragma unroll
        for (int j = 0; j < 4; j++) acc2[i][j] = 0ull;
#pragma unroll
    for (int kk = 0; kk < 64; kk++) {
        float4 a04 = *(const float4*)&Qs[kk][ty << 3];
        float4 a14 = *(const float4*)&Qs[kk][(ty << 3) + 4];
        float4 b04 = *(const float4*)&Ks[kk][tx << 3];
        float4 b14 = *(const float4*)&Ks[kk][(tx << 3) + 4];
        ull b2[4] = {pk2(b04.x, b04.y), pk2(b04.z, b04.w),
                     pk2(b14.x, b14.y), pk2(b14.z, b14.w)};
        float av[8] = {a04.x, a04.y, a04.z, a04.w, a14.x, a14.y, a14.z, a14.w};
#pragma unroll
        for (int i = 0; i < 8; i++) {
            ull ad = pk2(av[i], av[i]);
#pragma unroll
            for (int j = 0; j < 4; j++) fma2(acc2[i][j], ad, b2[j]);
        }
    }
    const float scale = 0.125f;
#pragma unroll
    for (int i = 0; i < 8; i++) {
        int irow = i0 + (ty << 3) + i;
#pragma unroll
        for (int j2 = 0; j2 < 2; j2++) {
            int jcol = j0 + (tx << 3) + j2 * 4;
            if (jcol < JTOT) {
                float2 p0 = upk2(acc2[i][j2 * 2]);
                float2 p1 = upk2(acc2[i][j2 * 2 + 1]);
                float4 v = make_float4(p0.x * scale, p0.y * scale,
                                       p1.x * scale, p1.y * scale);
                *(float4*)&g_dots[b][h][irow][jcol] = v;
            }
        }
    }
}

// ============ fused per-row attention: 1024 threads, f32x2 premix ============
#define ATTN_SMEM_FLOATS (H*JTOT + 256 + 256 + H*64*8 + 32 + 16 + 512)
#define ATTN_SMEM_INTS   (JTOT + JTOT)
#define ATTN_SMEM_BYTES  ((ATTN_SMEM_FLOATS + ATTN_SMEM_INTS) * 4)

#define INS8(vv) do { float _v = (vv); \
    if (_v > t8[7]) { t8[7] = _v; \
        _Pragma("unroll") \
        for (int _q = 7; _q >= 1; _q--) \
            if (t8[_q] > t8[_q-1]) { float _t = t8[_q]; t8[_q] = t8[_q-1]; t8[_q-1] = _t; } \
    } } while (0)

__global__ __launch_bounds__(1024) void attn_kernel(
    const float* __restrict__ pre, const float* __restrict__ post) {
    const int i = (NSEQ - 1) - blockIdx.x;
    const int b = blockIdx.y;
    const int tid = threadIdx.x;
    extern __shared__ float sm[];
    float* s_d    = sm;
    float* s_pre  = s_d + H * JTOT;
    float* s_post = s_pre + 256;
    float* s_top  = s_post + 256;
    float* s_zred = s_top + H * 64 * 8;
    float* s_inv  = s_zred + 32;
    ull*   s_pre2 = (ull*)(s_inv + 16);
    int* s_flag = (int*)(s_pre2 + 256);
    int* s_list = s_flag + JTOT;
    __shared__ int s_wsum[32];

    if (tid < 256) {
        float w = pre[tid];
        s_pre[tid]  = w;
        s_pre2[tid] = pk2(w, w);
        s_post[tid] = post[tid];
    }
    const int nv = i + NM + 1;
    __syncthreads();

    {
        const float* dbase = &g_dots[b][0][i][0];
        const long hstride = (long)NSEQ * JTOT;
        const int npair = (nv + 1) >> 1;
        for (int p = tid; p < npair; p += 1024) {
            int j = p << 1;
            s_flag[j] = 0;
            if (j + 1 < nv) {
                s_flag[j + 1] = 0;
                ull r2[16];
#pragma unroll
                for (int h2 = 0; h2 < 16; h2++)
                    r2[h2] = *(const ull*)&dbase[h2 * hstride + j];
#pragma unroll
                for (int k = 0; k < 16; k++) {
                    ull a2 = 0ull;
#pragma unroll
                    for (int h2 = 0; h2 < 16; h2++)
                        fma2(a2, r2[h2], s_pre2[h2 * 16 + k]);
                    *(ull*)&s_d[k * JTOT + j] = a2;
                }
            } else {
                float r1[16];
#pragma unroll
                for (int h2 = 0; h2 < 16; h2++) r1[h2] = dbase[h2 * hstride + j];
#pragma unroll
                for (int k = 0; k < 16; k++) {
                    float a = 0.f;
#pragma unroll
                    for (int h2 = 0; h2 < 16; h2++) a += r1[h2] * s_pre[h2 * 16 + k];
                    s_d[k * JTOT + j] = a;
                }
            }
        }
    }
    __syncthreads();

    const int row = tid >> 6;
    const int t64 = tid & 63;
    const float* rd = s_d + row * JTOT;
    float t8[8];
#pragma unroll
    for (int q = 0; q < 8; q++) t8[q] = -FLT_MAX;
    {
        const int n4 = nv >> 2;
        for (int q = t64; q < n4; q += 64) {
            float4 v4 = *(const float4*)&rd[q << 2];
            INS8(v4.x); INS8(v4.y); INS8(v4.z); INS8(v4.w);
        }
        int tail = nv & 3;
        if (t64 < tail) INS8(rd[(n4 << 2) + t64]);
    }
    {
        float* myl = s_top + (row * 64 + t64) * 8;
#pragma unroll
        for (int q = 0; q < 8; q++) myl[q] = t8[q];
    }
    __syncthreads();
    if (t64 < 32) {
        float* A  = s_top + (row * 64 + t64) * 8;
        float* B2 = s_top + (row * 64 + t64 + 32) * 8;
        float out[8];
        int ia = 0, ib = 0;
#pragma unroll
        for (int r2 = 0; r2 < 8; r2++) {
            float va = A[ia];
            float vb = B2[ib];
            bool ta = (va >= vb);
            out[r2] = ta ? va : vb;
            ia += ta ? 1 : 0;
            ib += ta ? 0 : 1;
        }
#pragma unroll
        for (int r2 = 0; r2 < 8; r2++) A[r2] = out[r2];
    }
    __syncthreads();
    if (t64 < 32) {
#pragma unroll
        for (int L = 16; L >= 1; L >>= 1) {
            if (t64 < L) {
                float* A  = s_top + (row * 64 + t64) * 8;
                float* B2 = s_top + (row * 64 + t64 + L) * 8;
                float out[8];
                int ia = 0, ib = 0;
#pragma unroll
                for (int r2 = 0; r2 < 8; r2++) {
                    float va = A[ia];
                    float vb = B2[ib];
                    bool ta = (va >= vb);
                    out[r2] = ta ? va : vb;
                    ia += ta ? 1 : 0;
                    ib += ta ? 0 : 1;
                }
#pragma unroll
                for (int r2 = 0; r2 < 8; r2++) A[r2] = out[r2];
            }
            __syncwarp();
        }
    }
    __syncthreads();
    const float thr = s_top[row * 512 + 7];
    const float mx  = s_top[row * 512 + 0];

    float psum = 0.f;
    {
        float* wrow = s_d + row * JTOT;
        const int np2 = nv >> 1;
        for (int q = t64; q < np2; q += 64) {
            int j = q << 1;
            float2 v = *(const float2*)&wrow[j];
            bool k0 = (v.x >= thr), k1 = (v.y >= thr);
            float e0 = k0 ? __expf(v.x - mx) : 0.f;
            float e1 = k1 ? __expf(v.y - mx) : 0.f;
            psum += e0; psum += e1;
            *(float2*)&wrow[j] = make_float2(e0, e1);
            if (k0) s_flag[j] = 1;
            if (k1) s_flag[j + 1] = 1;
        }
        if ((nv & 1) && t64 == 0) {
            int j = nv - 1;
            float v = wrow[j];
            if (v >= thr) { float e = __expf(v - mx); psum += e; wrow[j] = e; s_flag[j] = 1; }
            else wrow[j] = 0.f;
        }
    }
#pragma unroll
    for (int off = 16; off >= 1; off >>= 1)
        psum += __shfl_down_sync(0xffffffffu, psum, off);
    if ((tid & 31) == 0) s_zred[tid >> 5] = psum;
    __syncthreads();
    if (t64 == 0) s_inv[row] = 1.f / (s_zred[row * 2] + s_zred[row * 2 + 1]);

    const int lane = tid & 31;
    const int wid  = tid >> 5;
    const int CH = 3;
    int base = tid * CH;
    int end = base + CH; if (end > nv) end = nv;
    int c = 0;
    for (int j = base; j < end; j++) c += s_flag[j];
    int val = c;
#pragma unroll
    for (int off = 1; off < 32; off <<= 1) {
        int u = __shfl_up_sync(0xffffffffu, val, off);
        if (lane >= off) val += u;
    }
    if (lane == 31) s_wsum[wid] = val;
    __syncthreads();
    if (tid < 32) {
        int v = s_wsum[tid];
#pragma unroll
        for (int off = 1; off < 32; off <<= 1) {
            int u = __shfl_up_sync(0xffffffffu, v, off);
            if (tid >= off) v += u;
        }
        s_wsum[tid] = v;
    }
    __syncthreads();
    {
        int pos = (wid > 0 ? s_wsum[wid - 1] : 0) + (val - c);
        for (int j = base; j < end; j++)
            if (s_flag[j]) s_list[pos++] = j;
    }
    const int cnt = s_wsum[31];
    __syncthreads();

    for (int sI = tid; sI < cnt; sI += 1024) {
        int j = s_list[sI];
        float a[16];
#pragma unroll
        for (int h2 = 0; h2 < 16; h2++) a[h2] = s_d[h2 * JTOT + j] * s_inv[h2];
#pragma unroll
        for (int k = 0; k < 16; k++) {
            float acc2 = 0.f;
#pragma unroll
            for (int h2 = 0; h2 < 16; h2++) acc2 += a[h2] * s_post[h2 * 16 + k];
            s_d[k * JTOT + j] = acc2;
        }
    }
    __syncthreads();

    const int kk2 = tid >> 6;
    const int d = tid & 63;
    float acc = 0.f;
    const float* Vb = &g_V[b][kk2][0][0];
    const float* wr = s_d + kk2 * JTOT;
    int s2 = 0;
    for (; s2 + 3 < cnt; s2 += 4) {
        int4 j4 = *(const int4*)&s_list[s2];
        float w0 = wr[j4.x], w1 = wr[j4.y], w2 = wr[j4.z], w3 = wr[j4.w];
        float v0 = Vb[j4.x * 64 + d];
        float v1 = Vb[j4.y * 64 + d];
        float v2 = Vb[j4.z * 64 + d];
        float v3 = Vb[j4.w * 64 + d];
        acc += w0 * v0 + w1 * v1;
        acc += w2 * v2 + w3 * v3;
    }
    for (; s2 < cnt; s2++) {
        int ja = s_list[s2];
        acc += wr[ja] * Vb[ja * 64 + d];
    }
    bf16 hx, lx;
    bsplit2(acc, hx, lx);
    long off2 = (long)(b * NSEQ + i) * DIM + kk2 * 64 + d;
    g_ctxh[off2] = hx;
    g_ctxl[off2] = lx;
}

// ============ output projection: bf16x3 wmma + bias (linear path) ============
__global__ __launch_bounds__(256) void out_wmma(const float* __restrict__ bo,
                                                float* __restrict__ outp) {
    __shared__ float sEpi[128 * 72];
    bf16* sAh = (bf16*)sEpi;
    bf16* sAl = sAh + 128 * 40;
    bf16* sBh = sAl + 128 * 40;
    bf16* sBl = sBh + 32 * 72;
    const int m0 = blockIdx.y << 7;
    const int n0 = blockIdx.x << 6;
    const int tid = threadIdx.x;
    const int w = tid >> 5;
    const int wm = w >> 1, wn = w & 1;

    wmma::fragment<wmma::accumulator, 16, 16, 16, float> acc[2][2];
#pragma unroll
    for (int i = 0; i < 2; i++)
#pragma unroll
        for (int j = 0; j < 2; j++) wmma::fill_fragment(acc[i][j], 0.f);

    for (int k0 = 0; k0 < DIM; k0 += 32) {
        __syncthreads();
#pragma unroll
        for (int it = 0; it < 4; it++) {
            int idx = tid + it * 256;
            int r = idx >> 3, c = (idx & 7) << 2;
            long g = (long)(m0 + r) * DIM + k0 + c;
            *(uint2*)&sAh[r * 40 + c] = *(const uint2*)&g_ctxh[g];
            *(uint2*)&sAl[r * 40 + c] = *(const uint2*)&g_ctxl[g];
        }
#pragma unroll
        for (int it = 0; it < 2; it++) {
            int idx = tid + it * 256;
            int r = idx >> 4, c = (idx & 15) << 2;
            long g = (long)(k0 + r) * DIM + n0 + c;
            *(uint2*)&sBh[r * 72 + c] = *(const uint2*)&g_Woh[g];
            *(uint2*)&sBl[r * 72 + c] = *(const uint2*)&g_Wol[g];
        }
        __syncthreads();
#pragma unroll
        for (int ks = 0; ks < 2; ks++) {
            int k = ks << 4;
            wmma::fragment<wmma::matrix_a, 16, 16, 16, bf16, wmma::row_major> ah[2], al[2];
            wmma::fragment<wmma::matrix_b, 16, 16, 16, bf16, wmma::row_major> bh[2], bl[2];
#pragma unroll
            for (int fm = 0; fm < 2; fm++) {
                wmma::load_matrix_sync(ah[fm], &sAh[(wm * 32 + fm * 16) * 40 + k], 40);
                wmma::load_matrix_sync(al[fm], &sAl[(wm * 32 + fm * 16) * 40 + k], 40);
            }
#pragma unroll
            for (int fn = 0; fn < 2; fn++) {
                wmma::load_matrix_sync(bh[fn], &sBh[k * 72 + wn * 32 + fn * 16], 72);
                wmma::load_matrix_sync(bl[fn], &sBl[k * 72 + wn * 32 + fn * 16], 72);
            }
#pragma unroll
            for (int fm = 0; fm < 2; fm++)
#pragma unroll
                for (int fn = 0; fn < 2; fn++) {
                    wmma::mma_sync(acc[fm][fn], ah[fm], bl[fn], acc[fm][fn]);
                    wmma::mma_sync(acc[fm][fn], al[fm], bh[fn], acc[fm][fn]);
                    wmma::mma_sync(acc[fm][fn], ah[fm], bh[fn], acc[fm][fn]);
                }
        }
    }
    __syncthreads();
#pragma unroll
    for (int fm = 0; fm < 2; fm++)
#pragma unroll
        for (int fn = 0; fn < 2; fn++)
            wmma::store_matrix_sync(&sEpi[(wm * 32 + fm * 16) * 72 + wn * 32 + fn * 16],
                                    acc[fm][fn], 72, wmma::mem_row_major);
    __syncthreads();
#pragma unroll
    for (int it = 0; it < 8; it++) {
        int idx = tid + it * 256;
        int r = idx >> 4, c = (idx & 15) << 2;
        float4 v = *(const float4*)&sEpi[r * 72 + c];
        float4 bias = *(const float4*)&bo[n0 + c];
        v.x += bias.x; v.y += bias.y; v.z += bias.z; v.w += bias.w;
        *(float4*)&outp[(m0 + r) * DIM + n0 + c] = v;
    }
}

// ---------------- launch ----------------
extern "C" void kernel_launch(void* const* d_in, const int* in_sizes, int n_in,
                              void* d_out, int out_size) {
    const float* x    = (const float*)d_in[0];
    const float* Wq   = (const float*)d_in[1];
    const float* Wk   = (const float*)d_in[2];
    const float* Wv   = (const float*)d_in[3];
    const float* pre  = (const float*)d_in[4];
    const float* post = (const float*)d_in[5];
    const float* mk   = (const float*)d_in[6];
    const float* mv   = (const float*)d_in[7];
    const float* Wo   = (const float*)d_in[8];
    const float* bo   = (const float*)d_in[9];
    float* out = (float*)d_out;

    cudaFuncSetAttribute(attn_kernel, cudaFuncAttributeMaxDynamicSharedMemorySize, ATTN_SMEM_BYTES);

    memfill_kernel<<<(BATCH * H * NM * DH + 255) / 256, 256>>>(mk, mv);
    split_all<<<(NX4 + 2 * NW4 + 255) / 256, 256>>>(x, Wv, Wo);
    qkv_fused<<<1024, 256, QKV_FUSED_SMEM>>>(x, Wq, Wk);   // QK fp32 + V bf16x3, pipe-overlapped
    dots_kernel<<<dim3((JTOT + 127) / 128, NSEQ / 128, BATCH * H), 256>>>();
    attn_kernel<<<dim3(NSEQ, BATCH), 1024, ATTN_SMEM_BYTES>>>(pre, post);
    out_wmma<<<dim3(DIM / 64, MROWS / 128), 256>>>(bo, out);
}